// round 1
// baseline (speedup 1.0000x reference)
#include <cuda_runtime.h>
#include <cstdint>

#define FILL_I (-1000000)

// ---------------- static scratch (no allocations allowed) ----------------
// weight tables: rows 0..255  : 3840->256 (hx width)
//                rows 256..319: 3840->64  (mx width)
//                rows 320..575: 2160->256 (hx height)
//                rows 576..639: 2160->64  (mx height)
__device__ float g_w[640][128];
__device__ int   g_ws[640];
__device__ int   g_wc[640];

__device__ float g_tmpA[3 * 2160 * 256];   // width-reduced to 256
__device__ float g_tmpB[3 * 2160 * 64];    // width-reduced to 64
__device__ float g_hx[3 * 256 * 256];      // h_x
__device__ float g_mx[3 * 64 * 64];        // m_x
__device__ float g_mk[64 * 64];            // thresholded mask conv
__device__ float g_heat[256 * 256];        // final heatmap
__device__ unsigned g_bits[256 * 8];       // per-row peak bitmasks
__device__ int   g_coords[256 * 2];
__device__ float g_survive[256];

// output layout (float32):
// [0,65536)        heatmap
// [65536,66048)    coords (ri,ci interleaved)
// [66048,66304)    survive
// [66304,68096)    logits 256x7
// [68096,68352)    labels
#define OFF_COORDS 65536
#define OFF_SURV   66048
#define OFF_LOGITS 66304
#define OFF_LABELS 68096

// ---------------- K0: resize weight tables (jax compute_weight_mat) -------
__global__ void k_weights() {
    int t = threadIdx.x;
    if (t >= 640) return;
    int in, out, o;
    if (t < 256)      { in = 3840; out = 256; o = t; }
    else if (t < 320) { in = 3840; out = 64;  o = t - 256; }
    else if (t < 576) { in = 2160; out = 256; o = t - 320; }
    else              { in = 2160; out = 64;  o = t - 576; }
    float inv = (float)in / (float)out;          // 15, 60, 8.4375, 33.75
    float ks  = inv;                             // antialias kernel scale (>1)
    float sample = ((float)o + 0.5f) * inv - 0.5f;
    int s = (int)ceilf(sample - ks); if (s < 0) s = 0;
    int e = (int)floorf(sample + ks); if (e > in - 1) e = in - 1;
    int n = e - s + 1; if (n > 128) n = 128;
    float sum = 0.f;
    for (int k = 0; k < n; k++) {
        float d = fabsf(sample - (float)(s + k)) / ks;
        float w = 1.0f - d; if (w < 0.f) w = 0.f;
        g_w[t][k] = w; sum += w;
    }
    float r = 1.0f / sum;
    for (int k = 0; k < n; k++) g_w[t][k] *= r;
    g_ws[t] = s; g_wc[t] = n;
}

// ---------------- K1: horizontal pass (reads full input ONCE) -------------
__global__ void k_hresize(const float* __restrict__ x) {
    __shared__ float row[3840];
    int b = blockIdx.x;
    int c = b / 2160;
    int iy = b - c * 2160;
    const float* src = x + ((size_t)(c * 2160 + iy)) * 3840;
    for (int i = threadIdx.x; i < 3840; i += 320) row[i] = src[i];
    __syncthreads();
    int t = threadIdx.x;
    if (t < 256) {
        int s = g_ws[t], n = g_wc[t];
        float acc = 0.f;
        const float* w = g_w[t];
        for (int k = 0; k < n; k++) acc = fmaf(w[k], row[s + k], acc);
        g_tmpA[((size_t)(c * 2160 + iy)) * 256 + t] = acc;
    } else {
        int o = t - 256; int wi = 256 + o;
        int s = g_ws[wi], n = g_wc[wi];
        float acc = 0.f;
        const float* w = g_w[wi];
        for (int k = 0; k < n; k++) acc = fmaf(w[k], row[s + k], acc);
        g_tmpB[((size_t)(c * 2160 + iy)) * 64 + o] = acc;
    }
}

// ---------------- K2: vertical pass -> h_x (3,256,256) --------------------
__global__ void k_vresize_h() {
    int b = blockIdx.x;
    int ch = b >> 8, oy = b & 255;
    int wi = 320 + oy;
    int s = g_ws[wi], n = g_wc[wi];
    int ox = threadIdx.x;
    const float* w = g_w[wi];
    float acc = 0.f;
    for (int k = 0; k < n; k++)
        acc = fmaf(w[k], g_tmpA[((size_t)(ch * 2160 + s + k)) * 256 + ox], acc);
    g_hx[(ch * 256 + oy) * 256 + ox] = acc;
}

// ---------------- K3: vertical pass -> m_x (3,64,64) ----------------------
__global__ void k_vresize_m() {
    int b = blockIdx.x;
    int ch = b >> 6, oy = b & 63;
    int wi = 576 + oy;
    int s = g_ws[wi], n = g_wc[wi];
    int ox = threadIdx.x;
    const float* w = g_w[wi];
    float acc = 0.f;
    for (int k = 0; k < n; k++)
        acc = fmaf(w[k], g_tmpB[((size_t)(ch * 2160 + s + k)) * 64 + ox], acc);
    g_mx[(ch * 64 + oy) * 64 + ox] = acc;
}

// ---------------- K4a: mask conv 3x3 SAME on 64x64, thresh 0.6 ------------
__global__ void k_maskconv(const float* __restrict__ mw, const float* __restrict__ mb) {
    int r = blockIdx.x, c = threadIdx.x;
    float acc = mb[0];
    #pragma unroll
    for (int ic = 0; ic < 3; ic++)
        #pragma unroll
        for (int kr = 0; kr < 3; kr++) {
            int rr = r + kr - 1;
            if (rr < 0 || rr > 63) continue;
            #pragma unroll
            for (int kc = 0; kc < 3; kc++) {
                int cc = c + kc - 1;
                if (cc < 0 || cc > 63) continue;
                acc = fmaf(g_mx[(ic * 64 + rr) * 64 + cc], mw[ic * 9 + kr * 3 + kc], acc);
            }
        }
    float mk = fminf(fmaxf(acc, 0.f), 1.f);
    if (mk < 0.6f) mk = 0.f;
    g_mk[r * 64 + c] = mk;
}

// ---------------- K4b: loc conv 3x3 SAME 256x256 + heatmap ----------------
__global__ void k_heatmap(const float* __restrict__ lw, const float* __restrict__ lb,
                          float* __restrict__ out) {
    int r = blockIdx.x, c = threadIdx.x;
    float acc = lb[0];
    #pragma unroll
    for (int ic = 0; ic < 3; ic++)
        #pragma unroll
        for (int kr = 0; kr < 3; kr++) {
            int rr = r + kr - 1;
            if (rr < 0 || rr > 255) continue;
            #pragma unroll
            for (int kc = 0; kc < 3; kc++) {
                int cc = c + kc - 1;
                if (cc < 0 || cc > 255) continue;
                acc = fmaf(g_hx[(ic << 16) + rr * 256 + cc], lw[ic * 9 + kr * 3 + kc], acc);
            }
        }
    float hm = fminf(fmaxf(acc, 0.f), 1.f);
    if (hm < 0.4f) hm = 0.f;
    float h = hm * g_mk[(r >> 2) * 64 + (c >> 2)];
    g_heat[r * 256 + c] = h;
    out[r * 256 + c] = h;
}

// ---------------- K5a: peak flags -> per-row bitmasks ---------------------
__global__ void k_peakbits() {
    int r = blockIdx.x, c = threadIdx.x;
    int idx = r * 256 + c;
    float v = g_heat[idx];
    float l = (c > 0)   ? g_heat[idx - 1]   : 0.f;
    float rt = (c < 255) ? g_heat[idx + 1]   : 0.f;
    float u = (r > 0)   ? g_heat[idx - 256] : 0.f;
    float d = (r < 255) ? g_heat[idx + 256] : 0.f;
    bool pk = (v > l) && (v > rt) && (v > u) && (v > d);
    unsigned m = __ballot_sync(0xffffffffu, pk);
    if ((c & 31) == 0) g_bits[r * 8 + (c >> 5)] = m;
}

// ---------------- K5b: ordered compaction (single block) ------------------
__global__ void k_compact(float* __restrict__ out) {
    __shared__ int sc[256];
    int t = threadIdx.x;           // t = row
    unsigned b[8]; int cnt = 0;
    #pragma unroll
    for (int w = 0; w < 8; w++) { b[w] = g_bits[t * 8 + w]; cnt += __popc(b[w]); }
    sc[t] = cnt;
    __syncthreads();
    for (int off = 1; off < 256; off <<= 1) {
        int v = (t >= off) ? sc[t - off] : 0;
        __syncthreads();
        sc[t] += v;
        __syncthreads();
    }
    int excl = sc[t] - cnt;
    int tot = sc[255];
    int pos = excl;
    #pragma unroll
    for (int w = 0; w < 8; w++) {
        unsigned bits = b[w];
        while (bits) {
            int j = __ffs(bits) - 1; bits &= bits - 1;
            if (pos < 256) { g_coords[2 * pos] = t; g_coords[2 * pos + 1] = w * 32 + j; }
            pos++;
        }
    }
    if (t >= tot) { g_coords[2 * t] = FILL_I; g_coords[2 * t + 1] = FILL_I; }
    __syncthreads();
    out[OFF_COORDS + 2 * t]     = (float)g_coords[2 * t];
    out[OFF_COORDS + 2 * t + 1] = (float)g_coords[2 * t + 1];
}

// ---------------- K6: pairwise reject / survive ---------------------------
__global__ void k_survive(float* __restrict__ out) {
    __shared__ float cr[256], cc[256];
    __shared__ int   vs[256];
    int t = threadIdx.x;
    int ri = g_coords[2 * t], ci = g_coords[2 * t + 1];
    cr[t] = (float)ri; cc[t] = (float)ci;
    vs[t] = (ri > FILL_I) ? 1 : 0;
    __syncthreads();
    float x0 = cr[t], y0 = cc[t];
    int rej = 0;
    for (int i = 0; i < 256; i++) {
        float dx = cr[i] - x0, dy = cc[i] - y0;
        float d2 = dx * dx + dy * dy;
        rej |= (vs[i] && (d2 > 1.0f) && (d2 < 9.0f));
    }
    int sv = vs[t] && !rej;
    g_survive[t] = (float)sv;
    out[OFF_SURV + t] = (float)sv;
}

// ---------------- K7: window features -> linear -> softmax -> argmax ------
__global__ void k_classify(const float* __restrict__ W, const float* __restrict__ bias,
                           float* __restrict__ out) {
    int bx = blockIdx.x;
    int t = threadIdx.x;
    float sv = g_survive[bx];
    if (sv == 0.f) {
        if (t < 7) out[OFF_LOGITS + bx * 7 + t] = 0.f;
        if (t == 0) out[OFF_LABELS + bx] = 0.f;
        return;
    }
    int r0 = g_coords[2 * bx]; r0 = min(max(r0, 0), 255);
    int c0 = g_coords[2 * bx + 1]; c0 = min(max(c0, 0), 255);
    float part[7] = {0.f, 0.f, 0.f, 0.f, 0.f, 0.f, 0.f};
    for (int f = t; f < 3072; f += 256) {
        int ch = f >> 10, rem = f & 1023, wr = rem >> 5, wc = rem & 31;
        int rr = r0 + wr - 16, cc = c0 + wc - 16;
        float v = 0.f;
        if (rr >= 0 && rr < 256 && cc >= 0 && cc < 256)
            v = g_hx[(ch << 16) + rr * 256 + cc];
        const float* wrow = W + f * 7;
        #pragma unroll
        for (int k = 0; k < 7; k++) part[k] = fmaf(v, wrow[k], part[k]);
    }
    __shared__ float red[256 * 9];
    #pragma unroll
    for (int k = 0; k < 7; k++) red[t * 9 + k] = part[k];
    __syncthreads();
    for (int off = 128; off > 0; off >>= 1) {
        if (t < off)
            #pragma unroll
            for (int k = 0; k < 7; k++) red[t * 9 + k] += red[(t + off) * 9 + k];
        __syncthreads();
    }
    if (t == 0) {
        float l[7], e[7];
        float m = -1e30f;
        #pragma unroll
        for (int k = 0; k < 7; k++) { l[k] = red[k] + bias[k]; m = fmaxf(m, l[k]); }
        float s = 0.f;
        #pragma unroll
        for (int k = 0; k < 7; k++) { e[k] = expf(l[k] - m); s += e[k]; }
        float inv = 1.0f / s;
        int best = 0; float bv = -1e30f;
        #pragma unroll
        for (int k = 0; k < 7; k++) {
            float sm = e[k] * inv;
            out[OFF_LOGITS + bx * 7 + k] = sm;
            if (sm > bv) { bv = sm; best = k; }
        }
        out[OFF_LABELS + bx] = (float)best;
    }
}

// ---------------- launch ---------------------------------------------------
extern "C" void kernel_launch(void* const* d_in, const int* in_sizes, int n_in,
                              void* d_out, int out_size) {
    const float* x    = (const float*)d_in[0];
    const float* locw = (const float*)d_in[1];
    const float* locb = (const float*)d_in[2];
    const float* mskw = (const float*)d_in[3];
    const float* mskb = (const float*)d_in[4];
    const float* lblw = (const float*)d_in[5];
    const float* lblb = (const float*)d_in[6];
    float* out = (float*)d_out;

    k_weights<<<1, 640>>>();
    k_hresize<<<3 * 2160, 320>>>(x);
    k_vresize_h<<<3 * 256, 256>>>();
    k_vresize_m<<<3 * 64, 64>>>();
    k_maskconv<<<64, 64>>>(mskw, mskb);
    k_heatmap<<<256, 256>>>(locw, locb, out);
    k_peakbits<<<256, 256>>>();
    k_compact<<<1, 256>>>(out);
    k_survive<<<1, 256>>>(out);
    k_classify<<<256, 256>>>(lblw, lblb, out);
}

// round 2
// speedup vs baseline: 5.2655x; 5.2655x over previous
#include <cuda_runtime.h>
#include <cstdint>

#define FILL_I (-1000000)

// ---------------- static scratch --------------------------------------------
// Transposed, zero-padded weight tables (w[k][out]) + start indices.
#define NPAD_A 32    // 3840 -> 256 (width, h_x)
#define NPAD_B 120   // 3840 -> 64  (width, m_x)
#define NPAD_H 18    // 2160 -> 256 (height, h_x)
#define NPAD_M 68    // 2160 -> 64  (height, m_x)

__device__ float g_wA[NPAD_A][256];  __device__ int g_sA[256];
__device__ float g_wB[NPAD_B][64];   __device__ int g_sB[64];
__device__ float g_wH[NPAD_H][256];  __device__ int g_sH[256];
__device__ float g_wM[NPAD_M][64];   __device__ int g_sM[64];

__device__ float g_tmpA[3 * 2160 * 256];   // width-reduced to 256
__device__ float g_tmpB[3 * 2160 * 64];    // width-reduced to 64
__device__ float g_hx[3 * 256 * 256];      // h_x
__device__ float g_mx[3 * 64 * 64];        // m_x
__device__ float g_heat[256 * 256];        // final heatmap
__device__ unsigned g_bits[256 * 8];       // per-row peak bitmasks
__device__ int   g_coords[256 * 2];
__device__ float g_survive[256];

// output layout (float32):
#define OFF_COORDS 65536
#define OFF_SURV   66048
#define OFF_LOGITS 66304
#define OFF_LABELS 68096

// ---------------- K0: resize weight tables (jax compute_weight_mat) ---------
// 640 work items spread over 10 blocks so multiple SMs participate.
__global__ void k_weights() {
    int t = blockIdx.x * 64 + threadIdx.x;
    if (t >= 640) return;
    int in, out, o, cls;
    if (t < 256)      { in = 3840; out = 256; o = t;       cls = 0; }
    else if (t < 320) { in = 3840; out = 64;  o = t - 256; cls = 1; }
    else if (t < 576) { in = 2160; out = 256; o = t - 320; cls = 2; }
    else              { in = 2160; out = 64;  o = t - 576; cls = 3; }
    float inv = (float)in / (float)out;
    float ks  = inv;
    float sample = ((float)o + 0.5f) * inv - 0.5f;
    int s = (int)ceilf(sample - ks); if (s < 0) s = 0;
    int e = (int)floorf(sample + ks); if (e > in - 1) e = in - 1;
    int n = e - s + 1;
    float sum = 0.f;
    for (int k = 0; k < n; k++) {
        float d = fabsf(sample - (float)(s + k)) / ks;
        float w = 1.0f - d; if (w < 0.f) w = 0.f;
        sum += w;
    }
    float r = 1.0f / sum;
    // store normalized, zero-padded, transposed
    if (cls == 0) {
        g_sA[o] = s;
        for (int k = 0; k < NPAD_A; k++) {
            float w = 0.f;
            if (k < n) { float d = fabsf(sample - (float)(s + k)) / ks; w = fmaxf(1.0f - d, 0.f) * r; }
            g_wA[k][o] = w;
        }
    } else if (cls == 1) {
        g_sB[o] = s;
        for (int k = 0; k < NPAD_B; k++) {
            float w = 0.f;
            if (k < n) { float d = fabsf(sample - (float)(s + k)) / ks; w = fmaxf(1.0f - d, 0.f) * r; }
            g_wB[k][o] = w;
        }
    } else if (cls == 2) {
        g_sH[o] = s;
        for (int k = 0; k < NPAD_H; k++) {
            float w = 0.f;
            if (k < n) { float d = fabsf(sample - (float)(s + k)) / ks; w = fmaxf(1.0f - d, 0.f) * r; }
            g_wH[k][o] = w;
        }
    } else {
        g_sM[o] = s;
        for (int k = 0; k < NPAD_M; k++) {
            float w = 0.f;
            if (k < n) { float d = fabsf(sample - (float)(s + k)) / ks; w = fmaxf(1.0f - d, 0.f) * r; }
            g_wM[k][o] = w;
        }
    }
}

// ---------------- K1: horizontal pass (reads full input ONCE) ---------------
__global__ __launch_bounds__(320) void k_hresize(const float* __restrict__ x) {
    __shared__ float row[3840];
    int b = blockIdx.x;
    int c = b / 2160;
    int iy = b - c * 2160;
    const float4* src4 = (const float4*)(x + ((size_t)(c * 2160 + iy)) * 3840);
    float4* row4 = (float4*)row;
    for (int i = threadIdx.x; i < 960; i += 320) row4[i] = src4[i];
    __syncthreads();
    int t = threadIdx.x;
    if (t < 256) {
        int s = g_sA[t];
        float acc = 0.f;
        #pragma unroll
        for (int k = 0; k < NPAD_A; k++) {
            int idx = s + k; if (idx > 3839) idx = 3839;
            acc = fmaf(g_wA[k][t], row[idx], acc);
        }
        g_tmpA[((size_t)(c * 2160 + iy)) * 256 + t] = acc;
    } else {
        int o = t - 256;
        int s = g_sB[o];
        float acc = 0.f;
        #pragma unroll
        for (int k = 0; k < NPAD_B; k++) {
            int idx = s + k; if (idx > 3839) idx = 3839;
            acc = fmaf(g_wB[k][o], row[idx], acc);
        }
        g_tmpB[((size_t)(c * 2160 + iy)) * 64 + o] = acc;
    }
}

// ---------------- K2: fused vertical passes ---------------------------------
// blocks [0,768):   h_x rows   (ch = b>>8, oy = b&255), 256 threads = columns
// blocks [768,816): m_x rows packed 4 per block
__global__ __launch_bounds__(256) void k_vresize() {
    int b = blockIdx.x;
    int tid = threadIdx.x;
    if (b < 768) {
        int ch = b >> 8, oy = b & 255;
        int s = g_sH[oy];
        float acc = 0.f;
        #pragma unroll
        for (int k = 0; k < NPAD_H; k++) {
            int iy = s + k; if (iy > 2159) iy = 2159;
            acc = fmaf(g_wH[k][oy], g_tmpA[((size_t)(ch * 2160 + iy)) * 256 + tid], acc);
        }
        g_hx[(ch * 256 + oy) * 256 + tid] = acc;
    } else {
        int lin = (b - 768) * 4 + (tid >> 6);   // 0..191
        int ox = tid & 63;
        int ch = lin >> 6, oy = lin & 63;
        int s = g_sM[oy];
        float acc = 0.f;
        #pragma unroll
        for (int k = 0; k < NPAD_M; k++) {
            int iy = s + k; if (iy > 2159) iy = 2159;
            acc = fmaf(g_wM[k][oy], g_tmpB[((size_t)(ch * 2160 + iy)) * 64 + ox], acc);
        }
        g_mx[(ch * 64 + oy) * 64 + ox] = acc;
    }
}

// ---------------- K3: heatmap (loc conv + inline mask conv) -----------------
__global__ __launch_bounds__(256) void k_heatmap(const float* __restrict__ lw, const float* __restrict__ lb,
                                                 const float* __restrict__ mw, const float* __restrict__ mb,
                                                 float* __restrict__ out) {
    int r = blockIdx.x, c = threadIdx.x;

    // mask value at (r>>2, c>>2): 3x3 conv SAME on 64x64 m_x
    int mr = r >> 2, mc = c >> 2;
    float macc = mb[0];
    #pragma unroll
    for (int ic = 0; ic < 3; ic++)
        #pragma unroll
        for (int kr = 0; kr < 3; kr++) {
            int rr = mr + kr - 1;
            if (rr < 0 || rr > 63) continue;
            #pragma unroll
            for (int kc = 0; kc < 3; kc++) {
                int cc = mc + kc - 1;
                if (cc < 0 || cc > 63) continue;
                macc = fmaf(g_mx[(ic * 64 + rr) * 64 + cc], mw[ic * 9 + kr * 3 + kc], macc);
            }
        }
    float mk = fminf(fmaxf(macc, 0.f), 1.f);
    if (mk < 0.6f) mk = 0.f;

    // loc conv on 256x256 h_x
    float acc = lb[0];
    #pragma unroll
    for (int ic = 0; ic < 3; ic++)
        #pragma unroll
        for (int kr = 0; kr < 3; kr++) {
            int rr = r + kr - 1;
            if (rr < 0 || rr > 255) continue;
            #pragma unroll
            for (int kc = 0; kc < 3; kc++) {
                int cc = c + kc - 1;
                if (cc < 0 || cc > 255) continue;
                acc = fmaf(g_hx[(ic << 16) + rr * 256 + cc], lw[ic * 9 + kr * 3 + kc], acc);
            }
        }
    float hm = fminf(fmaxf(acc, 0.f), 1.f);
    if (hm < 0.4f) hm = 0.f;
    float h = hm * mk;
    g_heat[r * 256 + c] = h;
    out[r * 256 + c] = h;
}

// ---------------- K4: peak flags -> per-row bitmasks -------------------------
__global__ __launch_bounds__(256) void k_peakbits() {
    int r = blockIdx.x, c = threadIdx.x;
    int idx = r * 256 + c;
    float v = g_heat[idx];
    float l  = (c > 0)   ? g_heat[idx - 1]   : 0.f;
    float rt = (c < 255) ? g_heat[idx + 1]   : 0.f;
    float u  = (r > 0)   ? g_heat[idx - 256] : 0.f;
    float d  = (r < 255) ? g_heat[idx + 256] : 0.f;
    bool pk = (v > l) && (v > rt) && (v > u) && (v > d);
    unsigned m = __ballot_sync(0xffffffffu, pk);
    if ((c & 31) == 0) g_bits[r * 8 + (c >> 5)] = m;
}

// ---------------- K5: ordered compaction + pairwise survive (1 block) -------
__global__ __launch_bounds__(256) void k_compact_survive(float* __restrict__ out) {
    __shared__ int sc[256];
    __shared__ float cr[256], cc[256];
    __shared__ int   vs[256];
    int t = threadIdx.x;           // t = row
    unsigned b[8]; int cnt = 0;
    #pragma unroll
    for (int w = 0; w < 8; w++) { b[w] = g_bits[t * 8 + w]; cnt += __popc(b[w]); }
    sc[t] = cnt;
    __syncthreads();
    for (int off = 1; off < 256; off <<= 1) {
        int v = (t >= off) ? sc[t - off] : 0;
        __syncthreads();
        sc[t] += v;
        __syncthreads();
    }
    int excl = sc[t] - cnt;
    int tot = sc[255];
    int pos = excl;
    #pragma unroll
    for (int w = 0; w < 8; w++) {
        unsigned bits = b[w];
        while (bits) {
            int j = __ffs(bits) - 1; bits &= bits - 1;
            if (pos < 256) { g_coords[2 * pos] = t; g_coords[2 * pos + 1] = w * 32 + j; }
            pos++;
        }
    }
    if (t >= tot) { g_coords[2 * t] = FILL_I; g_coords[2 * t + 1] = FILL_I; }
    __syncthreads();

    int ri = g_coords[2 * t], ci = g_coords[2 * t + 1];
    out[OFF_COORDS + 2 * t]     = (float)ri;
    out[OFF_COORDS + 2 * t + 1] = (float)ci;
    cr[t] = (float)ri; cc[t] = (float)ci;
    vs[t] = (ri > FILL_I) ? 1 : 0;
    __syncthreads();
    float x0 = cr[t], y0 = cc[t];
    int rej = 0;
    #pragma unroll 8
    for (int i = 0; i < 256; i++) {
        float dx = cr[i] - x0, dy = cc[i] - y0;
        float d2 = dx * dx + dy * dy;
        rej |= (vs[i] && (d2 > 1.0f) && (d2 < 9.0f));
    }
    int sv = vs[t] && !rej;
    g_survive[t] = (float)sv;
    out[OFF_SURV + t] = (float)sv;
}

// ---------------- K6: window features -> linear -> softmax -> argmax --------
__global__ __launch_bounds__(256) void k_classify(const float* __restrict__ W, const float* __restrict__ bias,
                                                  float* __restrict__ out) {
    int bx = blockIdx.x;
    int t = threadIdx.x;
    float sv = g_survive[bx];
    if (sv == 0.f) {
        if (t < 7) out[OFF_LOGITS + bx * 7 + t] = 0.f;
        if (t == 0) out[OFF_LABELS + bx] = 0.f;
        return;
    }
    int r0 = g_coords[2 * bx]; r0 = min(max(r0, 0), 255);
    int c0 = g_coords[2 * bx + 1]; c0 = min(max(c0, 0), 255);
    float part[7] = {0.f, 0.f, 0.f, 0.f, 0.f, 0.f, 0.f};
    #pragma unroll
    for (int it = 0; it < 12; it++) {
        int f = t + it * 256;
        int ch = f >> 10, rem = f & 1023, wr = rem >> 5, wc = rem & 31;
        int rr = r0 + wr - 16, cc = c0 + wc - 16;
        float v = 0.f;
        if (rr >= 0 && rr < 256 && cc >= 0 && cc < 256)
            v = g_hx[(ch << 16) + rr * 256 + cc];
        const float* wrow = W + f * 7;
        #pragma unroll
        for (int k = 0; k < 7; k++) part[k] = fmaf(v, wrow[k], part[k]);
    }
    __shared__ float red[256 * 9];
    #pragma unroll
    for (int k = 0; k < 7; k++) red[t * 9 + k] = part[k];
    __syncthreads();
    for (int off = 128; off > 0; off >>= 1) {
        if (t < off)
            #pragma unroll
            for (int k = 0; k < 7; k++) red[t * 9 + k] += red[(t + off) * 9 + k];
        __syncthreads();
    }
    if (t == 0) {
        float l[7], e[7];
        float m = -1e30f;
        #pragma unroll
        for (int k = 0; k < 7; k++) { l[k] = red[k] + bias[k]; m = fmaxf(m, l[k]); }
        float s = 0.f;
        #pragma unroll
        for (int k = 0; k < 7; k++) { e[k] = expf(l[k] - m); s += e[k]; }
        float inv = 1.0f / s;
        int best = 0; float bv = -1e30f;
        #pragma unroll
        for (int k = 0; k < 7; k++) {
            float sm = e[k] * inv;
            out[OFF_LOGITS + bx * 7 + k] = sm;
            if (sm > bv) { bv = sm; best = k; }
        }
        out[OFF_LABELS + bx] = (float)best;
    }
}

// ---------------- launch ------------------------------------------------------
extern "C" void kernel_launch(void* const* d_in, const int* in_sizes, int n_in,
                              void* d_out, int out_size) {
    const float* x    = (const float*)d_in[0];
    const float* locw = (const float*)d_in[1];
    const float* locb = (const float*)d_in[2];
    const float* mskw = (const float*)d_in[3];
    const float* mskb = (const float*)d_in[4];
    const float* lblw = (const float*)d_in[5];
    const float* lblb = (const float*)d_in[6];
    float* out = (float*)d_out;

    k_weights<<<10, 64>>>();
    k_hresize<<<3 * 2160, 320>>>(x);
    k_vresize<<<816, 256>>>();
    k_heatmap<<<256, 256>>>(locw, locb, mskw, mskb, out);
    k_peakbits<<<256, 256>>>();
    k_compact_survive<<<1, 256>>>(out);
    k_classify<<<256, 256>>>(lblw, lblb, out);
}

// round 3
// speedup vs baseline: 5.2674x; 1.0003x over previous
#include <cuda_runtime.h>
#include <cstdint>

#define FILL_I (-1000000)

// ---------------- weight tables (transposed, zero-padded) -------------------
#define NPAD_A 32    // 3840 -> 256 (width, h_x)
#define NPAD_B 120   // 3840 -> 64  (width, m_x)  (always exactly 120 taps)
#define NPAD_H 18    // 2160 -> 256 (height, h_x)
#define NPAD_M 68    // 2160 -> 64  (height, m_x)

__device__ float g_wA[NPAD_A][256];  __device__ int g_sA[256];
__device__ float g_wB[NPAD_B][64];   __device__ int g_sB[64];
__device__ float g_wH[NPAD_H][256];  __device__ int g_sH[256];
__device__ float g_wM[NPAD_M][64];   __device__ int g_sM[64];

// padded with zero slack rows so vertical loops need no index clamp
__device__ float g_tmpA[(3 * 2160 + NPAD_H) * 256];
__device__ float g_tmpB[(3 * 2160 + NPAD_M) * 64];
__device__ float g_hx[3 * 256 * 256];
__device__ float g_mx[3 * 64 * 64];
__device__ unsigned g_bits[256 * 8];
__device__ int   g_coords[256 * 2];
__device__ float g_survive[256];

#define OFF_COORDS 65536
#define OFF_SURV   66048
#define OFF_LOGITS 66304
#define OFF_LABELS 68096

// ---------------- K0: resize weight tables ----------------------------------
__global__ void k_weights() {
    int t = blockIdx.x * 64 + threadIdx.x;
    if (t >= 640) return;
    int in, out, o, cls;
    if (t < 256)      { in = 3840; out = 256; o = t;       cls = 0; }
    else if (t < 320) { in = 3840; out = 64;  o = t - 256; cls = 1; }
    else if (t < 576) { in = 2160; out = 256; o = t - 320; cls = 2; }
    else              { in = 2160; out = 64;  o = t - 576; cls = 3; }
    float inv = (float)in / (float)out;
    float ks  = inv;
    float sample = ((float)o + 0.5f) * inv - 0.5f;
    int s = (int)ceilf(sample - ks); if (s < 0) s = 0;
    int e = (int)floorf(sample + ks); if (e > in - 1) e = in - 1;
    int n = e - s + 1;
    float sum = 0.f;
    for (int k = 0; k < n; k++) {
        float d = fabsf(sample - (float)(s + k)) / ks;
        sum += fmaxf(1.0f - d, 0.f);
    }
    float r = 1.0f / sum;
    if (cls == 0) {
        g_sA[o] = s;
        for (int k = 0; k < NPAD_A; k++) {
            float w = 0.f;
            if (k < n) { float d = fabsf(sample - (float)(s + k)) / ks; w = fmaxf(1.0f - d, 0.f) * r; }
            g_wA[k][o] = w;
        }
    } else if (cls == 1) {
        g_sB[o] = s;
        for (int k = 0; k < NPAD_B; k++) {
            float w = 0.f;
            if (k < n) { float d = fabsf(sample - (float)(s + k)) / ks; w = fmaxf(1.0f - d, 0.f) * r; }
            g_wB[k][o] = w;
        }
    } else if (cls == 2) {
        g_sH[o] = s;
        for (int k = 0; k < NPAD_H; k++) {
            float w = 0.f;
            if (k < n) { float d = fabsf(sample - (float)(s + k)) / ks; w = fmaxf(1.0f - d, 0.f) * r; }
            g_wH[k][o] = w;
        }
    } else {
        g_sM[o] = s;
        for (int k = 0; k < NPAD_M; k++) {
            float w = 0.f;
            if (k < n) { float d = fabsf(sample - (float)(s + k)) / ks; w = fmaxf(1.0f - d, 0.f) * r; }
            g_wM[k][o] = w;
        }
    }
}

// ---------------- K1: horizontal pass (full input read, once) ---------------
// 384 threads: [0,256) -> h_x widths (32 taps); [256,384) -> m_x widths,
// pair-split: 2 threads per output, 60 taps each, shfl_xor combine.
__global__ __launch_bounds__(384) void k_hresize(const float* __restrict__ x) {
    __shared__ float row[3968];          // 3840 data + zero tail (no clamp needed)
    int b = blockIdx.x;
    int c = b / 2160;
    int iy = b - c * 2160;
    const float4* src4 = (const float4*)(x + ((size_t)(c * 2160 + iy)) * 3840);
    float4* row4 = (float4*)row;
    for (int i = threadIdx.x; i < 992; i += 384)
        row4[i] = (i < 960) ? src4[i] : make_float4(0.f, 0.f, 0.f, 0.f);
    __syncthreads();
    int t = threadIdx.x;
    if (t < 256) {
        int s = g_sA[t];
        float acc = 0.f;
        #pragma unroll
        for (int k = 0; k < NPAD_A; k++)
            acc = fmaf(g_wA[k][t], row[s + k], acc);
        g_tmpA[((size_t)(c * 2160 + iy)) * 256 + t] = acc;
    } else {
        int p = t - 256;           // 0..127
        int o = p >> 1;            // output 0..63
        int half = p & 1;          // tap half
        int s = g_sB[o] + half * 60;
        float acc = 0.f;
        #pragma unroll
        for (int k = 0; k < 60; k++)
            acc = fmaf(g_wB[half * 60 + k][o], row[s + k], acc);
        acc += __shfl_xor_sync(0xffffffffu, acc, 1);
        if (half == 0)
            g_tmpB[((size_t)(c * 2160 + iy)) * 64 + o] = acc;
    }
}

// ---------------- K2: fused vertical passes (no clamps; zero-padded) --------
__global__ __launch_bounds__(256) void k_vresize() {
    int b = blockIdx.x;
    int tid = threadIdx.x;
    if (b < 768) {
        int ch = b >> 8, oy = b & 255;
        int s = g_sH[oy];
        float acc = 0.f;
        #pragma unroll
        for (int k = 0; k < NPAD_H; k++)
            acc = fmaf(g_wH[k][oy], g_tmpA[((size_t)(ch * 2160 + s + k)) * 256 + tid], acc);
        g_hx[(ch * 256 + oy) * 256 + tid] = acc;
    } else {
        int lin = (b - 768) * 4 + (tid >> 6);
        int ox = tid & 63;
        int ch = lin >> 6, oy = lin & 63;
        int s = g_sM[oy];
        float acc = 0.f;
        #pragma unroll
        for (int k = 0; k < NPAD_M; k++)
            acc = fmaf(g_wM[k][oy], g_tmpB[((size_t)(ch * 2160 + s + k)) * 64 + ox], acc);
        g_mx[(ch * 64 + oy) * 64 + ox] = acc;
    }
}

// ---------------- K3: fused heatmap conv + mask + peak detect ---------------
// 32 blocks x 8 output rows. Tile h_x in smem, conv via register sliding
// window, mask rows computed cooperatively, peaks + ballots in-block.
#define TW 258   // tile width: 256 + 2 halo cols
__global__ __launch_bounds__(256) void k_heatpeak(const float* __restrict__ lw, const float* __restrict__ lb,
                                                  const float* __restrict__ mw, const float* __restrict__ mb,
                                                  float* __restrict__ out) {
    __shared__ float sx[3][12][TW];     // input rows r0-2 .. r0+9, zero-padded
    __shared__ float sh[10][TW];        // heat rows r0-1 .. r0+8
    __shared__ float smask[4][64];      // mask rows r0/4-1 .. r0/4+2
    int tid = threadIdx.x;
    int r0 = blockIdx.x * 8;

    // stage h_x tile (coalesced), col offset +1
    for (int idx = tid; idx < 3 * 12 * 256; idx += 256) {
        int c = idx & 255;
        int i = (idx >> 8) % 12;
        int ch = idx / 3072;
        int gr = r0 - 2 + i;
        float v = (gr >= 0 && gr < 256) ? g_hx[(ch << 16) + gr * 256 + c] : 0.f;
        sx[ch][i][c + 1] = v;
    }
    // zero halo columns
    if (tid < 72) {
        int ch = tid / 24, i = (tid / 2) % 12, side = tid & 1;
        sx[ch][i][side ? (TW - 1) : 0] = 0.f;
    }
    if (tid < 20) {
        int j = tid >> 1, side = tid & 1;
        sh[j][side ? (TW - 1) : 0] = 0.f;
    }

    // mask conv: one value per thread (4 rows x 64 cols)
    {
        int mrow = (r0 >> 2) - 1 + (tid >> 6);
        int mcol = tid & 63;
        float v = 0.f;
        if (mrow >= 0 && mrow < 64) {
            float macc = mb[0];
            #pragma unroll
            for (int ic = 0; ic < 3; ic++)
                #pragma unroll
                for (int kr = 0; kr < 3; kr++) {
                    int rr = mrow + kr - 1;
                    if (rr < 0 || rr > 63) continue;
                    #pragma unroll
                    for (int kc = 0; kc < 3; kc++) {
                        int cc = mcol + kc - 1;
                        if (cc < 0 || cc > 63) continue;
                        macc = fmaf(g_mx[(ic * 64 + rr) * 64 + cc], mw[ic * 9 + kr * 3 + kc], macc);
                    }
                }
            v = fminf(fmaxf(macc, 0.f), 1.f);
            if (v < 0.6f) v = 0.f;
        }
        smask[tid >> 6][mcol] = v;
    }

    // conv weights to registers
    float w[27];
    #pragma unroll
    for (int k = 0; k < 27; k++) w[k] = lw[k];
    float bias = lb[0];
    __syncthreads();

    int c = tid;
    float acc[10];
    #pragma unroll
    for (int j = 0; j < 10; j++) acc[j] = bias;
    #pragma unroll
    for (int ch = 0; ch < 3; ch++) {
        #pragma unroll
        for (int i = 0; i < 12; i++) {
            float vm = sx[ch][i][c];
            float v0 = sx[ch][i][c + 1];
            float vp = sx[ch][i][c + 2];
            // kr=0 contributes to j=i; kr=1 -> j=i-1; kr=2 -> j=i-2
            if (i <= 9) {
                float h = fmaf(w[ch*9+0], vm, fmaf(w[ch*9+1], v0, w[ch*9+2] * vp));
                acc[i] += h;
            }
            if (i >= 1 && i <= 10) {
                float h = fmaf(w[ch*9+3], vm, fmaf(w[ch*9+4], v0, w[ch*9+5] * vp));
                acc[i-1] += h;
            }
            if (i >= 2) {
                float h = fmaf(w[ch*9+6], vm, fmaf(w[ch*9+7], v0, w[ch*9+8] * vp));
                acc[i-2] += h;
            }
        }
    }
    int mbase = (r0 >> 2) - 1;
    #pragma unroll
    for (int j = 0; j < 10; j++) {
        int rr = r0 - 1 + j;
        float heat = 0.f;
        if (rr >= 0 && rr < 256) {
            float hm = fminf(fmaxf(acc[j], 0.f), 1.f);
            if (hm < 0.4f) hm = 0.f;
            heat = hm * smask[(rr >> 2) - mbase][c >> 2];
        }
        sh[j][c + 1] = heat;
    }
    __syncthreads();

    // peaks for rows r0..r0+7 (j=1..8)
    #pragma unroll
    for (int j = 1; j <= 8; j++) {
        float v = sh[j][c + 1];
        bool pk = (v > sh[j][c]) && (v > sh[j][c + 2]) &&
                  (v > sh[j - 1][c + 1]) && (v > sh[j + 1][c + 1]);
        unsigned m = __ballot_sync(0xffffffffu, pk);
        if ((c & 31) == 0) g_bits[(r0 + j - 1) * 8 + (c >> 5)] = m;
        out[(r0 + j - 1) * 256 + c] = v;
    }
}

// ---------------- K4: ordered compaction + pairwise survive (1 block) -------
__global__ __launch_bounds__(256) void k_compact_survive(float* __restrict__ out) {
    __shared__ int sc[256];
    __shared__ float cr[256], cc[256];
    __shared__ int   vs[256];
    int t = threadIdx.x;
    unsigned b[8]; int cnt = 0;
    #pragma unroll
    for (int w = 0; w < 8; w++) { b[w] = g_bits[t * 8 + w]; cnt += __popc(b[w]); }
    sc[t] = cnt;
    __syncthreads();
    for (int off = 1; off < 256; off <<= 1) {
        int v = (t >= off) ? sc[t - off] : 0;
        __syncthreads();
        sc[t] += v;
        __syncthreads();
    }
    int excl = sc[t] - cnt;
    int tot = sc[255];
    int pos = excl;
    #pragma unroll
    for (int w = 0; w < 8; w++) {
        unsigned bits = b[w];
        while (bits) {
            int j = __ffs(bits) - 1; bits &= bits - 1;
            if (pos < 256) { g_coords[2 * pos] = t; g_coords[2 * pos + 1] = w * 32 + j; }
            pos++;
        }
    }
    if (t >= tot) { g_coords[2 * t] = FILL_I; g_coords[2 * t + 1] = FILL_I; }
    __syncthreads();

    int ri = g_coords[2 * t], ci = g_coords[2 * t + 1];
    out[OFF_COORDS + 2 * t]     = (float)ri;
    out[OFF_COORDS + 2 * t + 1] = (float)ci;
    cr[t] = (float)ri; cc[t] = (float)ci;
    vs[t] = (ri > FILL_I) ? 1 : 0;
    __syncthreads();
    float x0 = cr[t], y0 = cc[t];
    int rej = 0;
    #pragma unroll 8
    for (int i = 0; i < 256; i++) {
        float dx = cr[i] - x0, dy = cc[i] - y0;
        float d2 = dx * dx + dy * dy;
        rej |= (vs[i] && (d2 > 1.0f) && (d2 < 9.0f));
    }
    int sv = vs[t] && !rej;
    g_survive[t] = (float)sv;
    out[OFF_SURV + t] = (float)sv;
}

// ---------------- K5: window -> linear -> softmax -> argmax -----------------
__global__ __launch_bounds__(256) void k_classify(const float* __restrict__ W, const float* __restrict__ bias,
                                                  float* __restrict__ out) {
    int bx = blockIdx.x;
    int t = threadIdx.x;
    float sv = g_survive[bx];
    if (sv == 0.f) {
        if (t < 7) out[OFF_LOGITS + bx * 7 + t] = 0.f;
        if (t == 0) out[OFF_LABELS + bx] = 0.f;
        return;
    }
    int r0 = g_coords[2 * bx]; r0 = min(max(r0, 0), 255);
    int c0 = g_coords[2 * bx + 1]; c0 = min(max(c0, 0), 255);
    float part[7] = {0.f, 0.f, 0.f, 0.f, 0.f, 0.f, 0.f};
    #pragma unroll
    for (int it = 0; it < 12; it++) {
        int f = t + it * 256;
        int ch = f >> 10, rem = f & 1023, wr = rem >> 5, wc = rem & 31;
        int rr = r0 + wr - 16, cc = c0 + wc - 16;
        float v = 0.f;
        if (rr >= 0 && rr < 256 && cc >= 0 && cc < 256)
            v = g_hx[(ch << 16) + rr * 256 + cc];
        const float* wrow = W + f * 7;
        #pragma unroll
        for (int k = 0; k < 7; k++) part[k] = fmaf(v, wrow[k], part[k]);
    }
    __shared__ float red[256 * 9];
    #pragma unroll
    for (int k = 0; k < 7; k++) red[t * 9 + k] = part[k];
    __syncthreads();
    for (int off = 128; off > 0; off >>= 1) {
        if (t < off)
            #pragma unroll
            for (int k = 0; k < 7; k++) red[t * 9 + k] += red[(t + off) * 9 + k];
        __syncthreads();
    }
    if (t == 0) {
        float l[7], e[7];
        float m = -1e30f;
        #pragma unroll
        for (int k = 0; k < 7; k++) { l[k] = red[k] + bias[k]; m = fmaxf(m, l[k]); }
        float s = 0.f;
        #pragma unroll
        for (int k = 0; k < 7; k++) { e[k] = expf(l[k] - m); s += e[k]; }
        float inv = 1.0f / s;
        int best = 0; float bv = -1e30f;
        #pragma unroll
        for (int k = 0; k < 7; k++) {
            float sm = e[k] * inv;
            out[OFF_LOGITS + bx * 7 + k] = sm;
            if (sm > bv) { bv = sm; best = k; }
        }
        out[OFF_LABELS + bx] = (float)best;
    }
}

// ---------------- launch ------------------------------------------------------
extern "C" void kernel_launch(void* const* d_in, const int* in_sizes, int n_in,
                              void* d_out, int out_size) {
    const float* x    = (const float*)d_in[0];
    const float* locw = (const float*)d_in[1];
    const float* locb = (const float*)d_in[2];
    const float* mskw = (const float*)d_in[3];
    const float* mskb = (const float*)d_in[4];
    const float* lblw = (const float*)d_in[5];
    const float* lblb = (const float*)d_in[6];
    float* out = (float*)d_out;

    k_weights<<<10, 64>>>();
    k_hresize<<<3 * 2160, 384>>>(x);
    k_vresize<<<816, 256>>>();
    k_heatpeak<<<32, 256>>>(locw, locb, mskw, mskb, out);
    k_compact_survive<<<1, 256>>>(out);
    k_classify<<<256, 256>>>(lblw, lblb, out);
}

// round 4
// speedup vs baseline: 5.9258x; 1.1250x over previous
#include <cuda_runtime.h>
#include <cstdint>

#define FILL_I (-1000000)

// ---------------- weight tables (transposed, zero-padded) -------------------
#define NPAD_A 32    // 3840 -> 256 (width, h_x)
#define NPAD_B 120   // 3840 -> 64  (width, m_x)
#define NPAD_H 18    // 2160 -> 256 (height, h_x)
#define NPAD_M 68    // 2160 -> 64  (height, m_x)

__device__ float g_wA[NPAD_A][256];  __device__ int g_sA[256];
__device__ float g_wB[NPAD_B][64];   __device__ int g_sB[64];
__device__ float g_wH[NPAD_H][256];  __device__ int g_sH[256];
__device__ float g_wM[NPAD_M][64];   __device__ int g_sM[64];

// zero slack rows so vertical loops need no clamp
__device__ float g_tmpA[(3 * 2160 + NPAD_H) * 256];
__device__ float g_tmpB[(3 * 2160 + NPAD_M) * 64];
__device__ float g_hx[3 * 256 * 256];
__device__ float g_mx[3 * 64 * 64];
__device__ unsigned g_bits[256 * 8];
__device__ int   g_coords[256 * 2];
__device__ float g_survive[256];

#define OFF_COORDS 65536
#define OFF_SURV   66048
#define OFF_LOGITS 66304
#define OFF_LABELS 68096

// ---------------- K0: weights — one block per output, taps in parallel ------
__global__ __launch_bounds__(128) void k_weights() {
    int b = blockIdx.x, t = threadIdx.x;
    int in, out, o, cls;
    if (b < 256)      { in = 3840; out = 256; o = b;       cls = 0; }
    else if (b < 320) { in = 3840; out = 64;  o = b - 256; cls = 1; }
    else if (b < 576) { in = 2160; out = 256; o = b - 320; cls = 2; }
    else              { in = 2160; out = 64;  o = b - 576; cls = 3; }
    float inv = (float)in / (float)out;
    float ks  = inv;
    float sample = ((float)o + 0.5f) * inv - 0.5f;
    int s = (int)ceilf(sample - ks); if (s < 0) s = 0;
    int e = (int)floorf(sample + ks); if (e > in - 1) e = in - 1;
    int n = e - s + 1;
    float w = 0.f;
    if (t < n) {
        float d = fabsf(sample - (float)(s + t)) / ks;
        w = fmaxf(1.0f - d, 0.f);
    }
    __shared__ float red[128];
    red[t] = w;
    __syncthreads();
    #pragma unroll
    for (int off = 64; off > 0; off >>= 1) {
        if (t < off) red[t] += red[t + off];
        __syncthreads();
    }
    float wn = w / red[0];
    if (cls == 0)      { if (t < NPAD_A) g_wA[t][o] = wn; if (t == 0) g_sA[o] = s; }
    else if (cls == 1) { if (t < NPAD_B) g_wB[t][o] = wn; if (t == 0) g_sB[o] = s; }
    else if (cls == 2) { if (t < NPAD_H) g_wH[t][o] = wn; if (t == 0) g_sH[o] = s; }
    else               { if (t < NPAD_M) g_wM[t][o] = wn; if (t == 0) g_sM[o] = s; }
}

// ---------------- K1: horizontal pass — conflict-free both sides ------------
// 256 threads. Phase A: thread t -> h_x output t (32 taps, stride-15 lanes,
// conflict-free). Phase B: 4 threads per m_x output, interleaved taps k=q+4j
// (banks 60*o+q mod 32 all distinct -> conflict-free), shfl_xor combine.
__global__ __launch_bounds__(256) void k_hresize(const float* __restrict__ x) {
    __shared__ float row[3968];
    int b = blockIdx.x;
    int c = b / 2160;
    int iy = b - c * 2160;
    const float4* src4 = (const float4*)(x + ((size_t)(c * 2160 + iy)) * 3840);
    float4* row4 = (float4*)row;
    for (int i = threadIdx.x; i < 992; i += 256)
        row4[i] = (i < 960) ? src4[i] : make_float4(0.f, 0.f, 0.f, 0.f);
    __syncthreads();
    int t = threadIdx.x;
    // A side
    {
        int s = g_sA[t];
        float acc = 0.f;
        #pragma unroll
        for (int k = 0; k < NPAD_A; k++)
            acc = fmaf(g_wA[k][t], row[s + k], acc);
        g_tmpA[((size_t)(c * 2160 + iy)) * 256 + t] = acc;
    }
    // B side
    {
        int o = t >> 2, q = t & 3;
        int s = g_sB[o] + q;
        float acc = 0.f;
        #pragma unroll
        for (int j = 0; j < 30; j++)
            acc = fmaf(g_wB[q + 4 * j][o], row[s + 4 * j], acc);
        acc += __shfl_xor_sync(0xffffffffu, acc, 1);
        acc += __shfl_xor_sync(0xffffffffu, acc, 2);
        if (q == 0)
            g_tmpB[((size_t)(c * 2160 + iy)) * 64 + o] = acc;
    }
}

// ---------------- K2: fused vertical passes ---------------------------------
__global__ __launch_bounds__(256) void k_vresize() {
    int b = blockIdx.x;
    int tid = threadIdx.x;
    if (b < 768) {
        int ch = b >> 8, oy = b & 255;
        int s = g_sH[oy];
        float acc = 0.f;
        #pragma unroll
        for (int k = 0; k < NPAD_H; k++)
            acc = fmaf(g_wH[k][oy], g_tmpA[((size_t)(ch * 2160 + s + k)) * 256 + tid], acc);
        g_hx[(ch * 256 + oy) * 256 + tid] = acc;
    } else {
        int lin = (b - 768) * 4 + (tid >> 6);
        int ox = tid & 63;
        int ch = lin >> 6, oy = lin & 63;
        int s = g_sM[oy];
        float acc = 0.f;
        #pragma unroll
        for (int k = 0; k < NPAD_M; k++)
            acc = fmaf(g_wM[k][oy], g_tmpB[((size_t)(ch * 2160 + s + k)) * 64 + ox], acc);
        g_mx[(ch * 64 + oy) * 64 + ox] = acc;
    }
}

// ---------------- K3: heat conv + mask + peak, 1 row per block --------------
// Block r computes heat rows r-1..r+1 (redundant conv) and peak flags row r.
__global__ __launch_bounds__(256) void k_heatpeak(const float* __restrict__ lw, const float* __restrict__ lb,
                                                  const float* __restrict__ mw, const float* __restrict__ mb,
                                                  float* __restrict__ out) {
    __shared__ float sx[3][5][258];   // input rows r-2..r+2, col halo
    __shared__ float sh[3][258];      // heat rows r-1..r+1
    __shared__ float sm[2][64];       // mask rows (r-1)>>2, +1
    int tid = threadIdx.x;
    int r = blockIdx.x;

    // stage h_x rows
    for (int idx = tid; idx < 3 * 5 * 256; idx += 256) {
        int c = idx & 255;
        int i = (idx >> 8) % 5;
        int ch = idx / 1280;
        int gr = r - 2 + i;
        float v = (gr >= 0 && gr < 256) ? g_hx[(ch << 16) + gr * 256 + c] : 0.f;
        sx[ch][i][c + 1] = v;
    }
    if (tid < 30) { int ch = tid / 10, i = (tid / 2) % 5, side = tid & 1; sx[ch][i][side ? 257 : 0] = 0.f; }
    if (tid < 6)  { int j = tid >> 1, side = tid & 1; sh[j][side ? 257 : 0] = 0.f; }

    // mask rows: base = floor((r-1)/4), two rows, 128 threads
    int base = (r - 1) >> 2;
    if (tid < 128) {
        int mrow = base + (tid >> 6);
        int mcol = tid & 63;
        float v = 0.f;
        if (mrow >= 0 && mrow < 64) {
            float macc = mb[0];
            #pragma unroll
            for (int ic = 0; ic < 3; ic++)
                #pragma unroll
                for (int kr = 0; kr < 3; kr++) {
                    int rr = mrow + kr - 1;
                    if (rr < 0 || rr > 63) continue;
                    #pragma unroll
                    for (int kc = 0; kc < 3; kc++) {
                        int cc = mcol + kc - 1;
                        if (cc < 0 || cc > 63) continue;
                        macc = fmaf(g_mx[(ic * 64 + rr) * 64 + cc], mw[ic * 9 + kr * 3 + kc], macc);
                    }
                }
            v = fminf(fmaxf(macc, 0.f), 1.f);
            if (v < 0.6f) v = 0.f;
        }
        sm[tid >> 6][mcol] = v;
    }

    float w[27];
    #pragma unroll
    for (int k = 0; k < 27; k++) w[k] = lw[k];
    float bias = lb[0];
    __syncthreads();

    int c = tid;
    float acc[3] = {bias, bias, bias};
    #pragma unroll
    for (int ch = 0; ch < 3; ch++) {
        #pragma unroll
        for (int i = 0; i < 5; i++) {
            float vm = sx[ch][i][c];
            float v0 = sx[ch][i][c + 1];
            float vp = sx[ch][i][c + 2];
            // heat row j (global r-1+j) uses input row i with kr = i - j, j in [i-2, i]
            #pragma unroll
            for (int j = 0; j < 3; j++) {
                int kr = i - j;
                if (kr >= 0 && kr <= 2) {
                    acc[j] = fmaf(w[ch * 9 + kr * 3 + 0], vm,
                             fmaf(w[ch * 9 + kr * 3 + 1], v0,
                             fmaf(w[ch * 9 + kr * 3 + 2], vp, acc[j])));
                }
            }
        }
    }
    #pragma unroll
    for (int j = 0; j < 3; j++) {
        int rj = r - 1 + j;
        float heat = 0.f;
        if (rj >= 0 && rj < 256) {
            float hm = fminf(fmaxf(acc[j], 0.f), 1.f);
            if (hm < 0.4f) hm = 0.f;
            heat = hm * sm[(rj >> 2) - base][c >> 2];
        }
        sh[j][c + 1] = heat;
    }
    __syncthreads();

    float v = sh[1][c + 1];
    bool pk = (v > sh[1][c]) && (v > sh[1][c + 2]) &&
              (v > sh[0][c + 1]) && (v > sh[2][c + 1]);
    unsigned m = __ballot_sync(0xffffffffu, pk);
    if ((c & 31) == 0) g_bits[r * 8 + (c >> 5)] = m;
    out[r * 256 + c] = v;
}

// ---------------- K4: ordered compaction + pairwise survive (1 block) -------
__global__ __launch_bounds__(256) void k_compact_survive(float* __restrict__ out) {
    __shared__ int sc[256];
    __shared__ float cr[256], cc[256];
    __shared__ int   vs[256];
    int t = threadIdx.x;
    unsigned b[8]; int cnt = 0;
    #pragma unroll
    for (int w = 0; w < 8; w++) { b[w] = g_bits[t * 8 + w]; cnt += __popc(b[w]); }
    sc[t] = cnt;
    __syncthreads();
    for (int off = 1; off < 256; off <<= 1) {
        int v = (t >= off) ? sc[t - off] : 0;
        __syncthreads();
        sc[t] += v;
        __syncthreads();
    }
    int excl = sc[t] - cnt;
    int tot = sc[255];
    int pos = excl;
    #pragma unroll
    for (int w = 0; w < 8; w++) {
        unsigned bits = b[w];
        while (bits) {
            int j = __ffs(bits) - 1; bits &= bits - 1;
            if (pos < 256) { g_coords[2 * pos] = t; g_coords[2 * pos + 1] = w * 32 + j; }
            pos++;
        }
    }
    if (t >= tot) { g_coords[2 * t] = FILL_I; g_coords[2 * t + 1] = FILL_I; }
    __syncthreads();

    int ri = g_coords[2 * t], ci = g_coords[2 * t + 1];
    out[OFF_COORDS + 2 * t]     = (float)ri;
    out[OFF_COORDS + 2 * t + 1] = (float)ci;
    cr[t] = (float)ri; cc[t] = (float)ci;
    vs[t] = (ri > FILL_I) ? 1 : 0;
    __syncthreads();
    float x0 = cr[t], y0 = cc[t];
    int rej = 0;
    #pragma unroll 8
    for (int i = 0; i < 256; i++) {
        float dx = cr[i] - x0, dy = cc[i] - y0;
        float d2 = dx * dx + dy * dy;
        rej |= (vs[i] && (d2 > 1.0f) && (d2 < 9.0f));
    }
    int sv = vs[t] && !rej;
    g_survive[t] = (float)sv;
    out[OFF_SURV + t] = (float)sv;
}

// ---------------- K5: window -> linear -> softmax -> argmax -----------------
__global__ __launch_bounds__(256) void k_classify(const float* __restrict__ W, const float* __restrict__ bias,
                                                  float* __restrict__ out) {
    int bx = blockIdx.x;
    int t = threadIdx.x;
    float sv = g_survive[bx];
    if (sv == 0.f) {
        if (t < 7) out[OFF_LOGITS + bx * 7 + t] = 0.f;
        if (t == 0) out[OFF_LABELS + bx] = 0.f;
        return;
    }
    int r0 = g_coords[2 * bx]; r0 = min(max(r0, 0), 255);
    int c0 = g_coords[2 * bx + 1]; c0 = min(max(c0, 0), 255);
    float part[7] = {0.f, 0.f, 0.f, 0.f, 0.f, 0.f, 0.f};
    #pragma unroll
    for (int it = 0; it < 12; it++) {
        int f = t + it * 256;
        int ch = f >> 10, rem = f & 1023, wr = rem >> 5, wc = rem & 31;
        int rr = r0 + wr - 16, cc = c0 + wc - 16;
        float v = 0.f;
        if (rr >= 0 && rr < 256 && cc >= 0 && cc < 256)
            v = g_hx[(ch << 16) + rr * 256 + cc];
        const float* wrow = W + f * 7;
        #pragma unroll
        for (int k = 0; k < 7; k++) part[k] = fmaf(v, wrow[k], part[k]);
    }
    __shared__ float red[256 * 9];
    #pragma unroll
    for (int k = 0; k < 7; k++) red[t * 9 + k] = part[k];
    __syncthreads();
    for (int off = 128; off > 0; off >>= 1) {
        if (t < off)
            #pragma unroll
            for (int k = 0; k < 7; k++) red[t * 9 + k] += red[(t + off) * 9 + k];
        __syncthreads();
    }
    if (t == 0) {
        float l[7], e[7];
        float m = -1e30f;
        #pragma unroll
        for (int k = 0; k < 7; k++) { l[k] = red[k] + bias[k]; m = fmaxf(m, l[k]); }
        float s = 0.f;
        #pragma unroll
        for (int k = 0; k < 7; k++) { e[k] = expf(l[k] - m); s += e[k]; }
        float inv = 1.0f / s;
        int best = 0; float bv = -1e30f;
        #pragma unroll
        for (int k = 0; k < 7; k++) {
            float smv = e[k] * inv;
            out[OFF_LOGITS + bx * 7 + k] = smv;
            if (smv > bv) { bv = smv; best = k; }
        }
        out[OFF_LABELS + bx] = (float)best;
    }
}

// ---------------- launch ------------------------------------------------------
extern "C" void kernel_launch(void* const* d_in, const int* in_sizes, int n_in,
                              void* d_out, int out_size) {
    const float* x    = (const float*)d_in[0];
    const float* locw = (const float*)d_in[1];
    const float* locb = (const float*)d_in[2];
    const float* mskw = (const float*)d_in[3];
    const float* mskb = (const float*)d_in[4];
    const float* lblw = (const float*)d_in[5];
    const float* lblb = (const float*)d_in[6];
    float* out = (float*)d_out;

    k_weights<<<640, 128>>>();
    k_hresize<<<3 * 2160, 256>>>(x);
    k_vresize<<<816, 256>>>();
    k_heatpeak<<<256, 256>>>(locw, locb, mskw, mskb, out);
    k_compact_survive<<<1, 256>>>(out);
    k_classify<<<256, 256>>>(lblw, lblb, out);
}

// round 5
// speedup vs baseline: 6.2377x; 1.0526x over previous
#include <cuda_runtime.h>
#include <cstdint>

#define FILL_I (-1000000)

// ---------------- weight tables (transposed, zero-padded) -------------------
#define NPAD_A 32    // 3840 -> 256 (width, h_x)
#define NPAD_B 120   // 3840 -> 64  (width, m_x)
#define NPAD_H 18    // 2160 -> 256 (height, h_x)
#define NPAD_M 68    // 2160 -> 64  (height, m_x)

__device__ float g_wA[NPAD_A][256];  __device__ int g_sA[256];
__device__ float g_wB[NPAD_B][64];   __device__ int g_sB[64];
__device__ float g_wH[NPAD_H][256];  __device__ int g_sH[256];
__device__ float g_wM[NPAD_M][64];   __device__ int g_sM[64];

// zero slack rows so vertical loops need no clamp
__device__ float g_tmpA[(3 * 2160 + NPAD_H) * 256];
__device__ float g_tmpB[(3 * 2160 + NPAD_M) * 64];
__device__ float g_hx[3 * 256 * 256];
__device__ float g_mx[3 * 64 * 64];
__device__ unsigned g_bits[256 * 8];
__device__ int   g_coords[256 * 2];
__device__ float g_survive[256];

#define OFF_COORDS 65536
#define OFF_SURV   66048
#define OFF_LOGITS 66304
#define OFF_LABELS 68096

// ---------------- K0: weights — one block per output, taps in parallel ------
__global__ __launch_bounds__(128) void k_weights() {
    int b = blockIdx.x, t = threadIdx.x;
    int in, out, o, cls;
    if (b < 256)      { in = 3840; out = 256; o = b;       cls = 0; }
    else if (b < 320) { in = 3840; out = 64;  o = b - 256; cls = 1; }
    else if (b < 576) { in = 2160; out = 256; o = b - 320; cls = 2; }
    else              { in = 2160; out = 64;  o = b - 576; cls = 3; }
    float inv = (float)in / (float)out;
    float ks  = inv;
    float sample = ((float)o + 0.5f) * inv - 0.5f;
    int s = (int)ceilf(sample - ks); if (s < 0) s = 0;
    int e = (int)floorf(sample + ks); if (e > in - 1) e = in - 1;
    int n = e - s + 1;
    float w = 0.f;
    if (t < n) {
        float d = fabsf(sample - (float)(s + t)) / ks;
        w = fmaxf(1.0f - d, 0.f);
    }
    __shared__ float red[128];
    red[t] = w;
    __syncthreads();
    #pragma unroll
    for (int off = 64; off > 0; off >>= 1) {
        if (t < off) red[t] += red[t + off];
        __syncthreads();
    }
    float wn = w / red[0];
    if (cls == 0)      { if (t < NPAD_A) g_wA[t][o] = wn; if (t == 0) g_sA[o] = s; }
    else if (cls == 1) { if (t < NPAD_B) g_wB[t][o] = wn; if (t == 0) g_sB[o] = s; }
    else if (cls == 2) { if (t < NPAD_H) g_wH[t][o] = wn; if (t == 0) g_sH[o] = s; }
    else               { if (t < NPAD_M) g_wM[t][o] = wn; if (t == 0) g_sM[o] = s; }
}

// ---------------- K1: horizontal pass — conflict-free both sides ------------
__global__ __launch_bounds__(256) void k_hresize(const float* __restrict__ x) {
    __shared__ float row[3968];
    int b = blockIdx.x;
    int c = b / 2160;
    int iy = b - c * 2160;
    const float4* src4 = (const float4*)(x + ((size_t)(c * 2160 + iy)) * 3840);
    float4* row4 = (float4*)row;
    for (int i = threadIdx.x; i < 992; i += 256)
        row4[i] = (i < 960) ? src4[i] : make_float4(0.f, 0.f, 0.f, 0.f);
    __syncthreads();
    int t = threadIdx.x;
    // A side: thread t -> output t, 32 taps, stride-15 lanes (conflict-free)
    {
        int s = g_sA[t];
        float acc = 0.f;
        #pragma unroll
        for (int k = 0; k < NPAD_A; k++)
            acc = fmaf(g_wA[k][t], row[s + k], acc);
        g_tmpA[((size_t)(c * 2160 + iy)) * 256 + t] = acc;
    }
    // B side: 4 threads/output, taps k=q+4j (conflict-free), shfl combine
    {
        int o = t >> 2, q = t & 3;
        int s = g_sB[o] + q;
        float acc = 0.f;
        #pragma unroll
        for (int j = 0; j < 30; j++)
            acc = fmaf(g_wB[q + 4 * j][o], row[s + 4 * j], acc);
        acc += __shfl_xor_sync(0xffffffffu, acc, 1);
        acc += __shfl_xor_sync(0xffffffffu, acc, 2);
        if (q == 0)
            g_tmpB[((size_t)(c * 2160 + iy)) * 64 + o] = acc;
    }
}

// ---------------- K2: fused vertical passes ---------------------------------
__global__ __launch_bounds__(256) void k_vresize() {
    int b = blockIdx.x;
    int tid = threadIdx.x;
    if (b < 768) {
        int ch = b >> 8, oy = b & 255;
        int s = g_sH[oy];
        float acc = 0.f;
        #pragma unroll
        for (int k = 0; k < NPAD_H; k++)
            acc = fmaf(g_wH[k][oy], g_tmpA[((size_t)(ch * 2160 + s + k)) * 256 + tid], acc);
        g_hx[(ch * 256 + oy) * 256 + tid] = acc;
    } else {
        int lin = (b - 768) * 4 + (tid >> 6);
        int ox = tid & 63;
        int ch = lin >> 6, oy = lin & 63;
        int s = g_sM[oy];
        float acc = 0.f;
        #pragma unroll
        for (int k = 0; k < NPAD_M; k++)
            acc = fmaf(g_wM[k][oy], g_tmpB[((size_t)(ch * 2160 + s + k)) * 64 + ox], acc);
        g_mx[(ch * 64 + oy) * 64 + ox] = acc;
    }
}

// ---------------- K3: heat conv + mask + peak, 1 row per block --------------
// All staging via float4; mask conv branchless from a zero-padded smem tile.
__global__ __launch_bounds__(256) void k_heatpeak(const float* __restrict__ lw, const float* __restrict__ lb,
                                                  const float* __restrict__ mw, const float* __restrict__ mb,
                                                  float* __restrict__ out) {
    __shared__ float sx[3][5][256];   // input rows r-2..r+2 (no halo; clamp in compute)
    __shared__ float smx[3][4][66];   // m_x rows base-1..base+2, zero-padded cols
    __shared__ float sh[3][258];      // heat rows r-1..r+1, col halo
    int tid = threadIdx.x;
    int r = blockIdx.x;
    int base = (r - 1) >> 2;          // first mask row index needed

    // stage h_x rows as float4 (3*5*64 = 960 float4)
    for (int idx = tid; idx < 960; idx += 256) {
        int c4 = idx & 63;
        int i = (idx >> 6) % 5;
        int ch = idx / 320;
        int gr = r - 2 + i;
        float4 v = make_float4(0.f, 0.f, 0.f, 0.f);
        if (gr >= 0 && gr < 256)
            v = *(const float4*)(g_hx + (ch << 16) + gr * 256 + c4 * 4);
        *(float4*)(&sx[ch][i][c4 * 4]) = v;
    }
    // stage m_x rows base-1..base+2 as float4 (3*4*16 = 192 float4), col offset +1
    if (tid < 192) {
        int c4 = tid & 15;
        int i = (tid >> 4) & 3;
        int ch = tid >> 6;
        int gr = base - 1 + i;
        float4 v = make_float4(0.f, 0.f, 0.f, 0.f);
        if (gr >= 0 && gr < 64)
            v = *(const float4*)(g_mx + (ch * 64 + gr) * 64 + c4 * 4);
        smx[ch][i][c4 * 4 + 1] = v.x;
        smx[ch][i][c4 * 4 + 2] = v.y;
        smx[ch][i][c4 * 4 + 3] = v.z;
        smx[ch][i][c4 * 4 + 4] = v.w;
    }
    if (tid < 24) { int ch = tid / 8, i = (tid >> 1) & 3, side = tid & 1; smx[ch][i][side ? 65 : 0] = 0.f; }
    if (tid < 6)  { int j = tid >> 1, side = tid & 1; sh[j][side ? 257 : 0] = 0.f; }

    float w[27];
    #pragma unroll
    for (int k = 0; k < 27; k++) w[k] = __ldg(lw + k);
    float bias = __ldg(lb);
    float mbias = __ldg(mb);
    float mwr[27];
    #pragma unroll
    for (int k = 0; k < 27; k++) mwr[k] = __ldg(mw + k);
    __syncthreads();

    // mask conv: rows base (local 1) and base+1 (local 2), branchless
    __shared__ float sm[2][64];
    if (tid < 128) {
        int li = 1 + (tid >> 6);      // local row 1 or 2
        int mcol = tid & 63;
        float macc = mbias;
        #pragma unroll
        for (int ic = 0; ic < 3; ic++)
            #pragma unroll
            for (int kr = 0; kr < 3; kr++)
                #pragma unroll
                for (int kc = 0; kc < 3; kc++)
                    macc = fmaf(smx[ic][li + kr - 1][mcol + kc], mwr[ic * 9 + kr * 3 + kc], macc);
        float v = fminf(fmaxf(macc, 0.f), 1.f);
        if (v < 0.6f) v = 0.f;
        sm[tid >> 6][mcol] = v;
    }
    __syncthreads();

    int c = tid;
    float acc[3] = {bias, bias, bias};
    #pragma unroll
    for (int ch = 0; ch < 3; ch++) {
        #pragma unroll
        for (int i = 0; i < 5; i++) {
            float vm = (c > 0)   ? sx[ch][i][c - 1] : 0.f;
            float v0 = sx[ch][i][c];
            float vp = (c < 255) ? sx[ch][i][c + 1] : 0.f;
            #pragma unroll
            for (int j = 0; j < 3; j++) {
                int kr = i - j;
                if (kr >= 0 && kr <= 2) {
                    acc[j] = fmaf(w[ch * 9 + kr * 3 + 0], vm,
                             fmaf(w[ch * 9 + kr * 3 + 1], v0,
                             fmaf(w[ch * 9 + kr * 3 + 2], vp, acc[j])));
                }
            }
        }
    }
    #pragma unroll
    for (int j = 0; j < 3; j++) {
        int rj = r - 1 + j;
        float heat = 0.f;
        if (rj >= 0 && rj < 256) {
            float hm = fminf(fmaxf(acc[j], 0.f), 1.f);
            if (hm < 0.4f) hm = 0.f;
            heat = hm * sm[(rj >> 2) - base][c >> 2];
        }
        sh[j][c + 1] = heat;
    }
    __syncthreads();

    float v = sh[1][c + 1];
    bool pk = (v > sh[1][c]) && (v > sh[1][c + 2]) &&
              (v > sh[0][c + 1]) && (v > sh[2][c + 1]);
    unsigned m = __ballot_sync(0xffffffffu, pk);
    if ((c & 31) == 0) g_bits[r * 8 + (c >> 5)] = m;
    out[r * 256 + c] = v;
}

// ---------------- K4: ordered compaction + pairwise survive (1 block) -------
__global__ __launch_bounds__(256) void k_compact_survive(float* __restrict__ out) {
    __shared__ int sc[256];
    __shared__ float cr[256], cc[256];
    __shared__ int   vs[256];
    int t = threadIdx.x;
    unsigned b[8]; int cnt = 0;
    #pragma unroll
    for (int w = 0; w < 8; w++) { b[w] = g_bits[t * 8 + w]; cnt += __popc(b[w]); }
    sc[t] = cnt;
    __syncthreads();
    for (int off = 1; off < 256; off <<= 1) {
        int v = (t >= off) ? sc[t - off] : 0;
        __syncthreads();
        sc[t] += v;
        __syncthreads();
    }
    int excl = sc[t] - cnt;
    int tot = sc[255];
    int pos = excl;
    #pragma unroll
    for (int w = 0; w < 8; w++) {
        unsigned bits = b[w];
        while (bits) {
            int j = __ffs(bits) - 1; bits &= bits - 1;
            if (pos < 256) { g_coords[2 * pos] = t; g_coords[2 * pos + 1] = w * 32 + j; }
            pos++;
        }
    }
    if (t >= tot) { g_coords[2 * t] = FILL_I; g_coords[2 * t + 1] = FILL_I; }
    __syncthreads();

    int ri = g_coords[2 * t], ci = g_coords[2 * t + 1];
    out[OFF_COORDS + 2 * t]     = (float)ri;
    out[OFF_COORDS + 2 * t + 1] = (float)ci;
    cr[t] = (float)ri; cc[t] = (float)ci;
    vs[t] = (ri > FILL_I) ? 1 : 0;
    __syncthreads();
    float x0 = cr[t], y0 = cc[t];
    int rej = 0;
    #pragma unroll 8
    for (int i = 0; i < 256; i++) {
        float dx = cr[i] - x0, dy = cc[i] - y0;
        float d2 = dx * dx + dy * dy;
        rej |= (vs[i] && (d2 > 1.0f) && (d2 < 9.0f));
    }
    int sv = vs[t] && !rej;
    g_survive[t] = (float)sv;
    out[OFF_SURV + t] = (float)sv;
}

// ---------------- K5: window -> linear -> softmax -> argmax -----------------
__global__ __launch_bounds__(256) void k_classify(const float* __restrict__ W, const float* __restrict__ bias,
                                                  float* __restrict__ out) {
    int bx = blockIdx.x;
    int t = threadIdx.x;
    float sv = g_survive[bx];
    if (sv == 0.f) {
        if (t < 7) out[OFF_LOGITS + bx * 7 + t] = 0.f;
        if (t == 0) out[OFF_LABELS + bx] = 0.f;
        return;
    }
    int r0 = g_coords[2 * bx]; r0 = min(max(r0, 0), 255);
    int c0 = g_coords[2 * bx + 1]; c0 = min(max(c0, 0), 255);
    float part[7] = {0.f, 0.f, 0.f, 0.f, 0.f, 0.f, 0.f};
    #pragma unroll
    for (int it = 0; it < 12; it++) {
        int f = t + it * 256;
        int ch = f >> 10, rem = f & 1023, wr = rem >> 5, wc = rem & 31;
        int rr = r0 + wr - 16, cc = c0 + wc - 16;
        float v = 0.f;
        if (rr >= 0 && rr < 256 && cc >= 0 && cc < 256)
            v = g_hx[(ch << 16) + rr * 256 + cc];
        const float* wrow = W + f * 7;
        #pragma unroll
        for (int k = 0; k < 7; k++) part[k] = fmaf(v, wrow[k], part[k]);
    }
    // warp reduction then cross-warp via smem
    #pragma unroll
    for (int off = 16; off > 0; off >>= 1)
        #pragma unroll
        for (int k = 0; k < 7; k++)
            part[k] += __shfl_down_sync(0xffffffffu, part[k], off);
    __shared__ float sw[8][7];
    if ((t & 31) == 0)
        #pragma unroll
        for (int k = 0; k < 7; k++) sw[t >> 5][k] = part[k];
    __syncthreads();
    if (t == 0) {
        float l[7], e[7];
        float m = -1e30f;
        #pragma unroll
        for (int k = 0; k < 7; k++) {
            float s = bias[k];
            #pragma unroll
            for (int wwi = 0; wwi < 8; wwi++) s += sw[wwi][k];
            l[k] = s; m = fmaxf(m, s);
        }
        float s = 0.f;
        #pragma unroll
        for (int k = 0; k < 7; k++) { e[k] = expf(l[k] - m); s += e[k]; }
        float inv = 1.0f / s;
        int best = 0; float bv = -1e30f;
        #pragma unroll
        for (int k = 0; k < 7; k++) {
            float smv = e[k] * inv;
            out[OFF_LOGITS + bx * 7 + k] = smv;
            if (smv > bv) { bv = smv; best = k; }
        }
        out[OFF_LABELS + bx] = (float)best;
    }
}

// ---------------- launch ------------------------------------------------------
extern "C" void kernel_launch(void* const* d_in, const int* in_sizes, int n_in,
                              void* d_out, int out_size) {
    const float* x    = (const float*)d_in[0];
    const float* locw = (const float*)d_in[1];
    const float* locb = (const float*)d_in[2];
    const float* mskw = (const float*)d_in[3];
    const float* mskb = (const float*)d_in[4];
    const float* lblw = (const float*)d_in[5];
    const float* lblb = (const float*)d_in[6];
    float* out = (float*)d_out;

    k_weights<<<640, 128>>>();
    k_hresize<<<3 * 2160, 256>>>(x);
    k_vresize<<<816, 256>>>();
    k_heatpeak<<<256, 256>>>(locw, locb, mskw, mskb, out);
    k_compact_survive<<<1, 256>>>(out);
    k_classify<<<256, 256>>>(lblw, lblb, out);
}

// round 6
// speedup vs baseline: 8.4654x; 1.3571x over previous
#include <cuda_runtime.h>
#include <cstdint>

#define FILL_I (-1000000)

// ---------------- static scratch --------------------------------------------
#define NPAD_H 18    // 2160 -> 256 vertical taps
#define NPAD_M 68    // 2160 -> 64  vertical taps

// zero slack rows so vertical loops need no index clamp
__device__ float g_tmpA[(3 * 2160 + NPAD_H) * 256];
__device__ float g_tmpB[(3 * 2160 + NPAD_M) * 64];
__device__ float g_hx[3 * 256 * 256];
__device__ float g_mx[3 * 64 * 64];
__device__ unsigned g_bits[256 * 8];

#define OFF_COORDS 65536
#define OFF_SURV   66048
#define OFF_LOGITS 66304
#define OFF_LABELS 68096

// ---------------- K1: horizontal pass, 2 rows/block, inline weights ---------
__global__ __launch_bounds__(256) void k_hresize(const float* __restrict__ x) {
    __shared__ float row[2][3968];
    int b = blockIdx.x;                 // 3240 blocks = 3ch * 1080 row-pairs
    int c = b / 1080;
    int iy = (b - c * 1080) * 2;
    const float4* src4 = (const float4*)(x + ((size_t)(c * 2160 + iy)) * 3840);
    for (int i = threadIdx.x; i < 1984; i += 256) {
        int rr = i < 992 ? 0 : 1;
        int j = i < 992 ? i : i - 992;
        float4 v = make_float4(0.f, 0.f, 0.f, 0.f);
        if (j < 960) v = src4[rr * 960 + j];
        *(float4*)(&row[rr][j * 4]) = v;
    }
    __syncthreads();
    int t = threadIdx.x;
    size_t rbase = (size_t)(c * 2160 + iy);
    // A side: output t, 3840->256, inv=15, sample = 15t+7 (integer)
    {
        float sample = (float)(15 * t + 7);
        int s = 15 * t - 8; if (s < 0) s = 0;
        float acc0 = 0.f, acc1 = 0.f, wsum = 0.f;
        #pragma unroll
        for (int k = 0; k < 32; k++) {
            int pos = s + k;
            float d = fabsf(sample - (float)pos) * (1.0f / 15.0f);
            float w = fmaxf(1.0f - d, 0.f);
            if (pos > 3839) w = 0.f;
            wsum += w;
            acc0 = fmaf(w, row[0][pos], acc0);
            acc1 = fmaf(w, row[1][pos], acc1);
        }
        float inv = 1.0f / wsum;
        g_tmpA[rbase * 256 + t]         = acc0 * inv;
        g_tmpA[(rbase + 1) * 256 + t]   = acc1 * inv;
    }
    // B side: 4 threads/output, 3840->64, inv=60, sample = 60o+29.5
    {
        int o = t >> 2, q = t & 3;
        float sample = fmaf(60.f, (float)o, 29.5f);
        int s = 60 * o - 30; if (s < 0) s = 0;
        float acc0 = 0.f, acc1 = 0.f, wsum = 0.f;
        #pragma unroll
        for (int j = 0; j < 30; j++) {
            int pos = s + q + 4 * j;
            float d = fabsf(sample - (float)pos) * (1.0f / 60.0f);
            float w = fmaxf(1.0f - d, 0.f);
            if (pos > 3839) w = 0.f;
            wsum += w;
            acc0 = fmaf(w, row[0][pos], acc0);
            acc1 = fmaf(w, row[1][pos], acc1);
        }
        acc0 += __shfl_xor_sync(0xffffffffu, acc0, 1);
        acc1 += __shfl_xor_sync(0xffffffffu, acc1, 1);
        wsum += __shfl_xor_sync(0xffffffffu, wsum, 1);
        acc0 += __shfl_xor_sync(0xffffffffu, acc0, 2);
        acc1 += __shfl_xor_sync(0xffffffffu, acc1, 2);
        wsum += __shfl_xor_sync(0xffffffffu, wsum, 2);
        if (q == 0) {
            float inv = 1.0f / wsum;
            g_tmpB[rbase * 64 + o]       = acc0 * inv;
            g_tmpB[(rbase + 1) * 64 + o] = acc1 * inv;
        }
    }
}

// ---------------- K2: fused vertical passes, inline weights -----------------
__global__ __launch_bounds__(256) void k_vresize() {
    int b = blockIdx.x;
    int tid = threadIdx.x;
    if (b < 768) {
        int ch = b >> 8, oy = b & 255;
        float sample = fmaf((float)oy + 0.5f, 8.4375f, -0.5f);
        int s = (int)ceilf(sample - 8.4375f); if (s < 0) s = 0;
        float acc = 0.f, wsum = 0.f;
        #pragma unroll
        for (int k = 0; k < NPAD_H; k++) {
            int pos = s + k;
            float d = fabsf(sample - (float)pos) * (1.0f / 8.4375f);
            float w = fmaxf(1.0f - d, 0.f);
            if (pos > 2159) w = 0.f;
            wsum += w;
            acc = fmaf(w, g_tmpA[((size_t)(ch * 2160 + pos)) * 256 + tid], acc);
        }
        g_hx[(ch * 256 + oy) * 256 + tid] = acc / wsum;
    } else {
        int lin = (b - 768) * 4 + (tid >> 6);
        int ox = tid & 63;
        int ch = lin >> 6, oy = lin & 63;
        float sample = fmaf((float)oy + 0.5f, 33.75f, -0.5f);
        int s = (int)ceilf(sample - 33.75f); if (s < 0) s = 0;
        float acc = 0.f, wsum = 0.f;
        #pragma unroll
        for (int k = 0; k < NPAD_M; k++) {
            int pos = s + k;
            float d = fabsf(sample - (float)pos) * (1.0f / 33.75f);
            float w = fmaxf(1.0f - d, 0.f);
            if (pos > 2159) w = 0.f;
            wsum += w;
            acc = fmaf(w, g_tmpB[((size_t)(ch * 2160 + pos)) * 64 + ox], acc);
        }
        g_mx[(ch * 64 + oy) * 64 + ox] = acc / wsum;
    }
}

// ---------------- K3: heat conv + mask + peak, 1 row per block --------------
__global__ __launch_bounds__(256) void k_heatpeak(const float* __restrict__ lw, const float* __restrict__ lb,
                                                  const float* __restrict__ mw, const float* __restrict__ mb,
                                                  float* __restrict__ out) {
    __shared__ float sx[3][5][256];
    __shared__ float smx[3][4][66];
    __shared__ float sh[3][258];
    int tid = threadIdx.x;
    int r = blockIdx.x;
    int base = (r - 1) >> 2;

    for (int idx = tid; idx < 960; idx += 256) {
        int c4 = idx & 63;
        int i = (idx >> 6) % 5;
        int ch = idx / 320;
        int gr = r - 2 + i;
        float4 v = make_float4(0.f, 0.f, 0.f, 0.f);
        if (gr >= 0 && gr < 256)
            v = *(const float4*)(g_hx + (ch << 16) + gr * 256 + c4 * 4);
        *(float4*)(&sx[ch][i][c4 * 4]) = v;
    }
    if (tid < 192) {
        int c4 = tid & 15;
        int i = (tid >> 4) & 3;
        int ch = tid >> 6;
        int gr = base - 1 + i;
        float4 v = make_float4(0.f, 0.f, 0.f, 0.f);
        if (gr >= 0 && gr < 64)
            v = *(const float4*)(g_mx + (ch * 64 + gr) * 64 + c4 * 4);
        smx[ch][i][c4 * 4 + 1] = v.x;
        smx[ch][i][c4 * 4 + 2] = v.y;
        smx[ch][i][c4 * 4 + 3] = v.z;
        smx[ch][i][c4 * 4 + 4] = v.w;
    }
    if (tid < 24) { int ch = tid / 8, i = (tid >> 1) & 3, side = tid & 1; smx[ch][i][side ? 65 : 0] = 0.f; }
    if (tid < 6)  { int j = tid >> 1, side = tid & 1; sh[j][side ? 257 : 0] = 0.f; }

    float w[27];
    #pragma unroll
    for (int k = 0; k < 27; k++) w[k] = __ldg(lw + k);
    float bias = __ldg(lb);
    float mbias = __ldg(mb);
    float mwr[27];
    #pragma unroll
    for (int k = 0; k < 27; k++) mwr[k] = __ldg(mw + k);
    __syncthreads();

    __shared__ float sm[2][64];
    if (tid < 128) {
        int li = 1 + (tid >> 6);
        int mcol = tid & 63;
        float macc = mbias;
        #pragma unroll
        for (int ic = 0; ic < 3; ic++)
            #pragma unroll
            for (int kr = 0; kr < 3; kr++)
                #pragma unroll
                for (int kc = 0; kc < 3; kc++)
                    macc = fmaf(smx[ic][li + kr - 1][mcol + kc], mwr[ic * 9 + kr * 3 + kc], macc);
        float v = fminf(fmaxf(macc, 0.f), 1.f);
        if (v < 0.6f) v = 0.f;
        sm[tid >> 6][mcol] = v;
    }
    __syncthreads();

    int c = tid;
    float acc[3] = {bias, bias, bias};
    #pragma unroll
    for (int ch = 0; ch < 3; ch++) {
        #pragma unroll
        for (int i = 0; i < 5; i++) {
            float vm = (c > 0)   ? sx[ch][i][c - 1] : 0.f;
            float v0 = sx[ch][i][c];
            float vp = (c < 255) ? sx[ch][i][c + 1] : 0.f;
            #pragma unroll
            for (int j = 0; j < 3; j++) {
                int kr = i - j;
                if (kr >= 0 && kr <= 2) {
                    acc[j] = fmaf(w[ch * 9 + kr * 3 + 0], vm,
                             fmaf(w[ch * 9 + kr * 3 + 1], v0,
                             fmaf(w[ch * 9 + kr * 3 + 2], vp, acc[j])));
                }
            }
        }
    }
    #pragma unroll
    for (int j = 0; j < 3; j++) {
        int rj = r - 1 + j;
        float heat = 0.f;
        if (rj >= 0 && rj < 256) {
            float hm = fminf(fmaxf(acc[j], 0.f), 1.f);
            if (hm < 0.4f) hm = 0.f;
            heat = hm * sm[(rj >> 2) - base][c >> 2];
        }
        sh[j][c + 1] = heat;
    }
    __syncthreads();

    float v = sh[1][c + 1];
    bool pk = (v > sh[1][c]) && (v > sh[1][c + 2]) &&
              (v > sh[0][c + 1]) && (v > sh[2][c + 1]);
    unsigned m = __ballot_sync(0xffffffffu, pk);
    if ((c & 31) == 0) g_bits[r * 8 + (c >> 5)] = m;
    out[r * 256 + c] = v;
}

// ---------------- K4: fused compact + survive + classify --------------------
// Every block re-derives coords from g_bits (cheap in-smem scan), computes its
// own survive via syncthreads_or; block 0 writes coords + survive arrays.
__global__ __launch_bounds__(256) void k_classify(const float* __restrict__ W, const float* __restrict__ bias,
                                                  float* __restrict__ out) {
    __shared__ int sc[256];
    __shared__ int sr[256], scc[256];
    int t = threadIdx.x, bx = blockIdx.x;

    unsigned bw[8]; int cnt = 0;
    #pragma unroll
    for (int w = 0; w < 8; w++) { bw[w] = g_bits[t * 8 + w]; cnt += __popc(bw[w]); }
    sc[t] = cnt;
    __syncthreads();
    for (int off = 1; off < 256; off <<= 1) {
        int v = (t >= off) ? sc[t - off] : 0;
        __syncthreads();
        sc[t] += v;
        __syncthreads();
    }
    int excl = sc[t] - cnt;
    int tot = sc[255];
    int pos = excl;
    #pragma unroll
    for (int w = 0; w < 8; w++) {
        unsigned bits = bw[w];
        while (bits) {
            int j = __ffs(bits) - 1; bits &= bits - 1;
            if (pos < 256) { sr[pos] = t; scc[pos] = w * 32 + j; }
            pos++;
        }
    }
    if (t >= tot) { sr[t] = FILL_I; scc[t] = FILL_I; }
    __syncthreads();

    // own survive via block-wide OR
    int vit = (sr[t] > FILL_I);
    float x0 = (float)sr[bx], y0 = (float)scc[bx];
    float dx = (float)sr[t] - x0, dy = (float)scc[t] - y0;
    float d2 = dx * dx + dy * dy;
    int rej = __syncthreads_or(vit && (d2 > 1.0f) && (d2 < 9.0f));
    int sv = (sr[bx] > FILL_I) && !rej;

    if (bx == 0) {
        out[OFF_COORDS + 2 * t]     = (float)sr[t];
        out[OFF_COORDS + 2 * t + 1] = (float)scc[t];
        float xa = (float)sr[t], ya = (float)scc[t];
        int rj = 0;
        #pragma unroll 8
        for (int i = 0; i < 256; i++) {
            int vi = (sr[i] > FILL_I);
            float ddx = (float)sr[i] - xa, ddy = (float)scc[i] - ya;
            float dd2 = ddx * ddx + ddy * ddy;
            rj |= (vi && (dd2 > 1.0f) && (dd2 < 9.0f));
        }
        out[OFF_SURV + t] = (float)(vit && !rj);
    }

    if (!sv) {
        if (t < 7) out[OFF_LOGITS + bx * 7 + t] = 0.f;
        if (t == 0) out[OFF_LABELS + bx] = 0.f;
        return;
    }
    int r0 = min(max(sr[bx], 0), 255);
    int c0 = min(max(scc[bx], 0), 255);
    float part[7] = {0.f, 0.f, 0.f, 0.f, 0.f, 0.f, 0.f};
    #pragma unroll
    for (int it = 0; it < 12; it++) {
        int f = t + it * 256;
        int ch = f >> 10, rem = f & 1023, wr = rem >> 5, wc = rem & 31;
        int rr = r0 + wr - 16, cc2 = c0 + wc - 16;
        float v = 0.f;
        if (rr >= 0 && rr < 256 && cc2 >= 0 && cc2 < 256)
            v = g_hx[(ch << 16) + rr * 256 + cc2];
        const float* wrow = W + f * 7;
        #pragma unroll
        for (int k = 0; k < 7; k++) part[k] = fmaf(v, wrow[k], part[k]);
    }
    #pragma unroll
    for (int off = 16; off > 0; off >>= 1)
        #pragma unroll
        for (int k = 0; k < 7; k++)
            part[k] += __shfl_down_sync(0xffffffffu, part[k], off);
    __shared__ float sw[8][7];
    if ((t & 31) == 0)
        #pragma unroll
        for (int k = 0; k < 7; k++) sw[t >> 5][k] = part[k];
    __syncthreads();
    if (t == 0) {
        float l[7], e[7];
        float m = -1e30f;
        #pragma unroll
        for (int k = 0; k < 7; k++) {
            float s = bias[k];
            #pragma unroll
            for (int wi = 0; wi < 8; wi++) s += sw[wi][k];
            l[k] = s; m = fmaxf(m, s);
        }
        float s = 0.f;
        #pragma unroll
        for (int k = 0; k < 7; k++) { e[k] = expf(l[k] - m); s += e[k]; }
        float inv = 1.0f / s;
        int best = 0; float bv = -1e30f;
        #pragma unroll
        for (int k = 0; k < 7; k++) {
            float smv = e[k] * inv;
            out[OFF_LOGITS + bx * 7 + k] = smv;
            if (smv > bv) { bv = smv; best = k; }
        }
        out[OFF_LABELS + bx] = (float)best;
    }
}

// ---------------- launch ------------------------------------------------------
extern "C" void kernel_launch(void* const* d_in, const int* in_sizes, int n_in,
                              void* d_out, int out_size) {
    const float* x    = (const float*)d_in[0];
    const float* locw = (const float*)d_in[1];
    const float* locb = (const float*)d_in[2];
    const float* mskw = (const float*)d_in[3];
    const float* mskb = (const float*)d_in[4];
    const float* lblw = (const float*)d_in[5];
    const float* lblb = (const float*)d_in[6];
    float* out = (float*)d_out;

    k_hresize<<<3240, 256>>>(x);
    k_vresize<<<816, 256>>>();
    k_heatpeak<<<256, 256>>>(locw, locb, mskw, mskb, out);
    k_classify<<<256, 256>>>(lblw, lblb, out);
}

// round 7
// speedup vs baseline: 9.0784x; 1.0724x over previous
#include <cuda_runtime.h>
#include <cstdint>

#define FILL_I (-1000000)

#define NPAD_H 18
#define NPAD_M 68

__device__ float g_tmpA[(3 * 2160 + NPAD_H) * 256];
__device__ float g_tmpB[(3 * 2160 + NPAD_M) * 64];
__device__ float g_hx[3 * 256 * 256];
__device__ float g_mx[3 * 64 * 64];
__device__ unsigned g_bits[256 * 8];
__device__ int   g_coords[256 * 2];
__device__ float g_survive[256];

#define OFF_COORDS 65536
#define OFF_SURV   66048
#define OFF_LOGITS 66304
#define OFF_LABELS 68096

// compile-time normalized triangle weights (interior outputs)
__device__ __forceinline__ constexpr float WAc(int k) {
    return (float)((15.0 - ((k < 15) ? (15 - k) : (k - 15))) / 225.0);
}
__device__ __forceinline__ constexpr float WBc(int k) {
    double d = (k < 60) ? (59.5 - k) : (k - 59.5);
    return (float)((60.0 - d) / 3600.0);
}

// ---------------- K1: horizontal pass, constant weights, guard bands --------
__global__ __launch_bounds__(256) void k_hresize(const float* __restrict__ x) {
    __shared__ float row[2][4032];      // [0,32) zero | data 32..3871 | [3872,4032) zero
    __shared__ float pb[4][2][64];      // B-side quarter partials
    int b = blockIdx.x;                 // 3240 = 3ch * 1080 row pairs
    int c = b / 1080;
    int iy = (b - c * 1080) * 2;
    const float4* src4 = (const float4*)(x + ((size_t)(c * 2160 + iy)) * 3840);
    for (int idx = threadIdx.x; idx < 2016; idx += 256) {
        int rr = idx < 1008 ? 0 : 1;
        int j = idx < 1008 ? idx : idx - 1008;
        float4 v = make_float4(0.f, 0.f, 0.f, 0.f);
        if (j >= 8 && j < 968) v = src4[rr * 960 + (j - 8)];
        *(float4*)(&row[rr][j * 4]) = v;
    }
    __syncthreads();
    int t = threadIdx.x;
    size_t rbase = (size_t)(c * 2160 + iy);

    // ---- A side: output t, taps k=1..29 at row[15t+24+k], constant weights
    {
        int sb = 15 * t + 24;
        float a0 = 0.f, a1 = 0.f;
        #pragma unroll
        for (int k = 1; k <= 29; k++) {
            a0 = fmaf(WAc(k), row[0][sb + k], a0);
            a1 = fmaf(WAc(k), row[1][sb + k], a1);
        }
        if (t == 0 || t == 255) { a0 *= (225.f / 197.f); a1 *= (225.f / 197.f); }
        g_tmpA[rbase * 256 + t]       = a0;
        g_tmpA[(rbase + 1) * 256 + t] = a1;
    }

    // ---- B side: output o=t&63, quarter q=t>>6 (warp-uniform), taps 30q..30q+29
    {
        int o = t & 63, q = t >> 6;
        int sb = 60 * o + 2;            // row index of tap k=0 (guard-banded)
        float b0 = 0.f, b1 = 0.f;
        #define BQ(K0)                                                    \
            _Pragma("unroll")                                             \
            for (int j = 0; j < 30; j++) {                                \
                b0 = fmaf(WBc((K0) + j), row[0][sb + (K0) + j], b0);      \
                b1 = fmaf(WBc((K0) + j), row[1][sb + (K0) + j], b1);      \
            }
        if      (q == 0) { BQ(0)  }
        else if (q == 1) { BQ(30) }
        else if (q == 2) { BQ(60) }
        else             { BQ(90) }
        #undef BQ
        pb[q][0][o] = b0;
        pb[q][1][o] = b1;
    }
    __syncthreads();
    if (t < 64) {
        float s0 = pb[0][0][t] + pb[1][0][t] + pb[2][0][t] + pb[3][0][t];
        float s1 = pb[0][1][t] + pb[1][1][t] + pb[2][1][t] + pb[3][1][t];
        if (t == 0 || t == 63) { s0 *= (8.f / 7.f); s1 *= (8.f / 7.f); }
        g_tmpB[rbase * 64 + t]       = s0;
        g_tmpB[(rbase + 1) * 64 + t] = s1;
    }
}

// ---------------- K2: fused vertical passes, inline weights -----------------
__global__ __launch_bounds__(256) void k_vresize() {
    int b = blockIdx.x;
    int tid = threadIdx.x;
    if (b < 768) {
        int ch = b >> 8, oy = b & 255;
        float sample = fmaf((float)oy + 0.5f, 8.4375f, -0.5f);
        int s = (int)ceilf(sample - 8.4375f); if (s < 0) s = 0;
        float acc = 0.f, wsum = 0.f;
        #pragma unroll
        for (int k = 0; k < NPAD_H; k++) {
            int pos = s + k;
            float d = fabsf(sample - (float)pos) * (1.0f / 8.4375f);
            float w = fmaxf(1.0f - d, 0.f);
            if (pos > 2159) w = 0.f;
            wsum += w;
            acc = fmaf(w, g_tmpA[((size_t)(ch * 2160 + pos)) * 256 + tid], acc);
        }
        g_hx[(ch * 256 + oy) * 256 + tid] = acc / wsum;
    } else {
        int lin = (b - 768) * 4 + (tid >> 6);
        int ox = tid & 63;
        int ch = lin >> 6, oy = lin & 63;
        float sample = fmaf((float)oy + 0.5f, 33.75f, -0.5f);
        int s = (int)ceilf(sample - 33.75f); if (s < 0) s = 0;
        float acc = 0.f, wsum = 0.f;
        #pragma unroll
        for (int k = 0; k < NPAD_M; k++) {
            int pos = s + k;
            float d = fabsf(sample - (float)pos) * (1.0f / 33.75f);
            float w = fmaxf(1.0f - d, 0.f);
            if (pos > 2159) w = 0.f;
            wsum += w;
            acc = fmaf(w, g_tmpB[((size_t)(ch * 2160 + pos)) * 64 + ox], acc);
        }
        g_mx[(ch * 64 + oy) * 64 + ox] = acc / wsum;
    }
}

// ---------------- K3: heat conv + mask + peak, 1 row per block --------------
__global__ __launch_bounds__(256) void k_heatpeak(const float* __restrict__ lw, const float* __restrict__ lb,
                                                  const float* __restrict__ mw, const float* __restrict__ mb,
                                                  float* __restrict__ out) {
    __shared__ float sx[3][5][256];
    __shared__ float smx[3][4][66];
    __shared__ float sh[3][258];
    int tid = threadIdx.x;
    int r = blockIdx.x;
    int base = (r - 1) >> 2;

    for (int idx = tid; idx < 960; idx += 256) {
        int c4 = idx & 63;
        int i = (idx >> 6) % 5;
        int ch = idx / 320;
        int gr = r - 2 + i;
        float4 v = make_float4(0.f, 0.f, 0.f, 0.f);
        if (gr >= 0 && gr < 256)
            v = *(const float4*)(g_hx + (ch << 16) + gr * 256 + c4 * 4);
        *(float4*)(&sx[ch][i][c4 * 4]) = v;
    }
    if (tid < 192) {
        int c4 = tid & 15;
        int i = (tid >> 4) & 3;
        int ch = tid >> 6;
        int gr = base - 1 + i;
        float4 v = make_float4(0.f, 0.f, 0.f, 0.f);
        if (gr >= 0 && gr < 64)
            v = *(const float4*)(g_mx + (ch * 64 + gr) * 64 + c4 * 4);
        smx[ch][i][c4 * 4 + 1] = v.x;
        smx[ch][i][c4 * 4 + 2] = v.y;
        smx[ch][i][c4 * 4 + 3] = v.z;
        smx[ch][i][c4 * 4 + 4] = v.w;
    }
    if (tid < 24) { int ch = tid / 8, i = (tid >> 1) & 3, side = tid & 1; smx[ch][i][side ? 65 : 0] = 0.f; }
    if (tid < 6)  { int j = tid >> 1, side = tid & 1; sh[j][side ? 257 : 0] = 0.f; }

    float w[27];
    #pragma unroll
    for (int k = 0; k < 27; k++) w[k] = __ldg(lw + k);
    float bias = __ldg(lb);
    float mbias = __ldg(mb);
    float mwr[27];
    #pragma unroll
    for (int k = 0; k < 27; k++) mwr[k] = __ldg(mw + k);
    __syncthreads();

    __shared__ float sm[2][64];
    if (tid < 128) {
        int li = 1 + (tid >> 6);
        int mcol = tid & 63;
        float macc = mbias;
        #pragma unroll
        for (int ic = 0; ic < 3; ic++)
            #pragma unroll
            for (int kr = 0; kr < 3; kr++)
                #pragma unroll
                for (int kc = 0; kc < 3; kc++)
                    macc = fmaf(smx[ic][li + kr - 1][mcol + kc], mwr[ic * 9 + kr * 3 + kc], macc);
        float v = fminf(fmaxf(macc, 0.f), 1.f);
        if (v < 0.6f) v = 0.f;
        sm[tid >> 6][mcol] = v;
    }
    __syncthreads();

    int c = tid;
    float acc[3] = {bias, bias, bias};
    #pragma unroll
    for (int ch = 0; ch < 3; ch++) {
        #pragma unroll
        for (int i = 0; i < 5; i++) {
            float vm = (c > 0)   ? sx[ch][i][c - 1] : 0.f;
            float v0 = sx[ch][i][c];
            float vp = (c < 255) ? sx[ch][i][c + 1] : 0.f;
            #pragma unroll
            for (int j = 0; j < 3; j++) {
                int kr = i - j;
                if (kr >= 0 && kr <= 2) {
                    acc[j] = fmaf(w[ch * 9 + kr * 3 + 0], vm,
                             fmaf(w[ch * 9 + kr * 3 + 1], v0,
                             fmaf(w[ch * 9 + kr * 3 + 2], vp, acc[j])));
                }
            }
        }
    }
    #pragma unroll
    for (int j = 0; j < 3; j++) {
        int rj = r - 1 + j;
        float heat = 0.f;
        if (rj >= 0 && rj < 256) {
            float hm = fminf(fmaxf(acc[j], 0.f), 1.f);
            if (hm < 0.4f) hm = 0.f;
            heat = hm * sm[(rj >> 2) - base][c >> 2];
        }
        sh[j][c + 1] = heat;
    }
    __syncthreads();

    float v = sh[1][c + 1];
    bool pk = (v > sh[1][c]) && (v > sh[1][c + 2]) &&
              (v > sh[0][c + 1]) && (v > sh[2][c + 1]);
    unsigned m = __ballot_sync(0xffffffffu, pk);
    if ((c & 31) == 0) g_bits[r * 8 + (c >> 5)] = m;
    out[r * 256 + c] = v;
}

// ---------------- K4: ordered compaction + pairwise survive (1 block) -------
__global__ __launch_bounds__(256) void k_compact_survive(float* __restrict__ out) {
    __shared__ int sc[256];
    __shared__ float cr[256], cc[256];
    __shared__ int   vs[256];
    int t = threadIdx.x;
    unsigned b[8]; int cnt = 0;
    #pragma unroll
    for (int w = 0; w < 8; w++) { b[w] = g_bits[t * 8 + w]; cnt += __popc(b[w]); }
    sc[t] = cnt;
    __syncthreads();
    for (int off = 1; off < 256; off <<= 1) {
        int v = (t >= off) ? sc[t - off] : 0;
        __syncthreads();
        sc[t] += v;
        __syncthreads();
    }
    int excl = sc[t] - cnt;
    int tot = sc[255];
    int pos = excl;
    #pragma unroll
    for (int w = 0; w < 8; w++) {
        unsigned bits = b[w];
        while (bits) {
            int j = __ffs(bits) - 1; bits &= bits - 1;
            if (pos < 256) { g_coords[2 * pos] = t; g_coords[2 * pos + 1] = w * 32 + j; }
            pos++;
        }
    }
    if (t >= tot) { g_coords[2 * t] = FILL_I; g_coords[2 * t + 1] = FILL_I; }
    __syncthreads();

    int ri = g_coords[2 * t], ci = g_coords[2 * t + 1];
    out[OFF_COORDS + 2 * t]     = (float)ri;
    out[OFF_COORDS + 2 * t + 1] = (float)ci;
    cr[t] = (float)ri; cc[t] = (float)ci;
    vs[t] = (ri > FILL_I) ? 1 : 0;
    __syncthreads();
    float x0 = cr[t], y0 = cc[t];
    int rej = 0;
    #pragma unroll 8
    for (int i = 0; i < 256; i++) {
        float dx = cr[i] - x0, dy = cc[i] - y0;
        float d2 = dx * dx + dy * dy;
        rej |= (vs[i] && (d2 > 1.0f) && (d2 < 9.0f));
    }
    int sv = vs[t] && !rej;
    g_survive[t] = (float)sv;
    out[OFF_SURV + t] = (float)sv;
}

// ---------------- K5: window -> linear -> softmax -> argmax -----------------
__global__ __launch_bounds__(256) void k_classify(const float* __restrict__ W, const float* __restrict__ bias,
                                                  float* __restrict__ out) {
    int bx = blockIdx.x;
    int t = threadIdx.x;
    float sv = g_survive[bx];
    if (sv == 0.f) {
        if (t < 7) out[OFF_LOGITS + bx * 7 + t] = 0.f;
        if (t == 0) out[OFF_LABELS + bx] = 0.f;
        return;
    }
    int r0 = min(max(g_coords[2 * bx], 0), 255);
    int c0 = min(max(g_coords[2 * bx + 1], 0), 255);
    float part[7] = {0.f, 0.f, 0.f, 0.f, 0.f, 0.f, 0.f};
    #pragma unroll
    for (int it = 0; it < 12; it++) {
        int f = t + it * 256;
        int ch = f >> 10, rem = f & 1023, wr = rem >> 5, wc = rem & 31;
        int rr = r0 + wr - 16, cc = c0 + wc - 16;
        float v = 0.f;
        if (rr >= 0 && rr < 256 && cc >= 0 && cc < 256)
            v = g_hx[(ch << 16) + rr * 256 + cc];
        const float* wrow = W + f * 7;
        #pragma unroll
        for (int k = 0; k < 7; k++) part[k] = fmaf(v, wrow[k], part[k]);
    }
    #pragma unroll
    for (int off = 16; off > 0; off >>= 1)
        #pragma unroll
        for (int k = 0; k < 7; k++)
            part[k] += __shfl_down_sync(0xffffffffu, part[k], off);
    __shared__ float sw[8][7];
    if ((t & 31) == 0)
        #pragma unroll
        for (int k = 0; k < 7; k++) sw[t >> 5][k] = part[k];
    __syncthreads();
    if (t == 0) {
        float l[7], e[7];
        float m = -1e30f;
        #pragma unroll
        for (int k = 0; k < 7; k++) {
            float s = bias[k];
            #pragma unroll
            for (int wi = 0; wi < 8; wi++) s += sw[wi][k];
            l[k] = s; m = fmaxf(m, s);
        }
        float s = 0.f;
        #pragma unroll
        for (int k = 0; k < 7; k++) { e[k] = expf(l[k] - m); s += e[k]; }
        float inv = 1.0f / s;
        int best = 0; float bv = -1e30f;
        #pragma unroll
        for (int k = 0; k < 7; k++) {
            float smv = e[k] * inv;
            out[OFF_LOGITS + bx * 7 + k] = smv;
            if (smv > bv) { bv = smv; best = k; }
        }
        out[OFF_LABELS + bx] = (float)best;
    }
}

// ---------------- launch ------------------------------------------------------
extern "C" void kernel_launch(void* const* d_in, const int* in_sizes, int n_in,
                              void* d_out, int out_size) {
    const float* x    = (const float*)d_in[0];
    const float* locw = (const float*)d_in[1];
    const float* locb = (const float*)d_in[2];
    const float* mskw = (const float*)d_in[3];
    const float* mskb = (const float*)d_in[4];
    const float* lblw = (const float*)d_in[5];
    const float* lblb = (const float*)d_in[6];
    float* out = (float*)d_out;

    k_hresize<<<3240, 256>>>(x);
    k_vresize<<<816, 256>>>();
    k_heatpeak<<<256, 256>>>(locw, locb, mskw, mskb, out);
    k_compact_survive<<<1, 256>>>(out);
    k_classify<<<256, 256>>>(lblw, lblb, out);
}

// round 8
// speedup vs baseline: 9.5289x; 1.0496x over previous
#include <cuda_runtime.h>
#include <cstdint>

#define FILL_I (-1000000)

#define NPAD_H 18
#define NPAD_M 68

__device__ float g_tmpA[(3 * 2160 + NPAD_H) * 256];
__device__ float g_tmpB[(3 * 2160 + NPAD_M) * 64];
__device__ float g_hx[3 * 256 * 256];
__device__ float g_mx[3 * 64 * 64];
__device__ unsigned g_bits[256 * 8];
__device__ int   g_coords[256 * 2];

#define OFF_COORDS 65536
#define OFF_SURV   66048
#define OFF_LOGITS 66304
#define OFF_LABELS 68096

// compile-time normalized triangle weights (interior outputs)
__device__ __forceinline__ constexpr float WAc(int k) {
    return (float)((15.0 - ((k < 15) ? (15 - k) : (k - 15))) / 225.0);
}
__device__ __forceinline__ constexpr float WBc(int k) {
    double d = (k < 60) ? (59.5 - k) : (k - 59.5);
    return (float)((60.0 - d) / 3600.0);
}

// ---------------- K1: horizontal pass, constant weights, guard bands --------
__global__ __launch_bounds__(256) void k_hresize(const float* __restrict__ x) {
    __shared__ float row[2][4032];      // [0,32) zero | data 32..3871 | zero tail
    __shared__ float pb[4][2][64];
    int b = blockIdx.x;                 // 3240 = 3ch * 1080 row pairs
    int c = b / 1080;
    int iy = (b - c * 1080) * 2;
    const float4* src4 = (const float4*)(x + ((size_t)(c * 2160 + iy)) * 3840);
    for (int idx = threadIdx.x; idx < 2016; idx += 256) {
        int rr = idx < 1008 ? 0 : 1;
        int j = idx < 1008 ? idx : idx - 1008;
        float4 v = make_float4(0.f, 0.f, 0.f, 0.f);
        if (j >= 8 && j < 968) v = src4[rr * 960 + (j - 8)];
        *(float4*)(&row[rr][j * 4]) = v;
    }
    __syncthreads();
    int t = threadIdx.x;
    size_t rbase = (size_t)(c * 2160 + iy);

    // A side: output t, taps k=1..29 at row[15t+24+k]
    {
        int sb = 15 * t + 24;
        float a0 = 0.f, a1 = 0.f;
        #pragma unroll
        for (int k = 1; k <= 29; k++) {
            a0 = fmaf(WAc(k), row[0][sb + k], a0);
            a1 = fmaf(WAc(k), row[1][sb + k], a1);
        }
        if (t == 0 || t == 255) { a0 *= (225.f / 197.f); a1 *= (225.f / 197.f); }
        g_tmpA[rbase * 256 + t]       = a0;
        g_tmpA[(rbase + 1) * 256 + t] = a1;
    }

    // B side: output o=t&63, quarter q=t>>6 (warp-uniform)
    {
        int o = t & 63, q = t >> 6;
        int sb = 60 * o + 2;
        float b0 = 0.f, b1 = 0.f;
        #define BQ(K0)                                                    \
            _Pragma("unroll")                                             \
            for (int j = 0; j < 30; j++) {                                \
                b0 = fmaf(WBc((K0) + j), row[0][sb + (K0) + j], b0);      \
                b1 = fmaf(WBc((K0) + j), row[1][sb + (K0) + j], b1);      \
            }
        if      (q == 0) { BQ(0)  }
        else if (q == 1) { BQ(30) }
        else if (q == 2) { BQ(60) }
        else             { BQ(90) }
        #undef BQ
        pb[q][0][o] = b0;
        pb[q][1][o] = b1;
    }
    __syncthreads();
    if (t < 64) {
        float s0 = pb[0][0][t] + pb[1][0][t] + pb[2][0][t] + pb[3][0][t];
        float s1 = pb[0][1][t] + pb[1][1][t] + pb[2][1][t] + pb[3][1][t];
        if (t == 0 || t == 63) { s0 *= (8.f / 7.f); s1 *= (8.f / 7.f); }
        g_tmpB[rbase * 64 + t]       = s0;
        g_tmpB[(rbase + 1) * 64 + t] = s1;
    }
}

// ---------------- K2: fused vertical passes, inline weights -----------------
__global__ __launch_bounds__(256) void k_vresize() {
    int b = blockIdx.x;
    int tid = threadIdx.x;
    if (b < 768) {
        int ch = b >> 8, oy = b & 255;
        float sample = fmaf((float)oy + 0.5f, 8.4375f, -0.5f);
        int s = (int)ceilf(sample - 8.4375f); if (s < 0) s = 0;
        float acc = 0.f, wsum = 0.f;
        #pragma unroll
        for (int k = 0; k < NPAD_H; k++) {
            int pos = s + k;
            float d = fabsf(sample - (float)pos) * (1.0f / 8.4375f);
            float w = fmaxf(1.0f - d, 0.f);
            if (pos > 2159) w = 0.f;
            wsum += w;
            acc = fmaf(w, g_tmpA[((size_t)(ch * 2160 + pos)) * 256 + tid], acc);
        }
        g_hx[(ch * 256 + oy) * 256 + tid] = acc / wsum;
    } else {
        int lin = (b - 768) * 4 + (tid >> 6);
        int ox = tid & 63;
        int ch = lin >> 6, oy = lin & 63;
        float sample = fmaf((float)oy + 0.5f, 33.75f, -0.5f);
        int s = (int)ceilf(sample - 33.75f); if (s < 0) s = 0;
        float acc = 0.f, wsum = 0.f;
        #pragma unroll
        for (int k = 0; k < NPAD_M; k++) {
            int pos = s + k;
            float d = fabsf(sample - (float)pos) * (1.0f / 33.75f);
            float w = fmaxf(1.0f - d, 0.f);
            if (pos > 2159) w = 0.f;
            wsum += w;
            acc = fmaf(w, g_tmpB[((size_t)(ch * 2160 + pos)) * 64 + ox], acc);
        }
        g_mx[(ch * 64 + oy) * 64 + ox] = acc / wsum;
    }
}

// ---------------- K3: heat conv + mask + peak, 1 row per block --------------
__global__ __launch_bounds__(256) void k_heatpeak(const float* __restrict__ lw, const float* __restrict__ lb,
                                                  const float* __restrict__ mw, const float* __restrict__ mb,
                                                  float* __restrict__ out) {
    __shared__ float sx[3][5][256];
    __shared__ float smx[3][4][66];
    __shared__ float sh[3][258];
    int tid = threadIdx.x;
    int r = blockIdx.x;
    int base = (r - 1) >> 2;

    for (int idx = tid; idx < 960; idx += 256) {
        int c4 = idx & 63;
        int i = (idx >> 6) % 5;
        int ch = idx / 320;
        int gr = r - 2 + i;
        float4 v = make_float4(0.f, 0.f, 0.f, 0.f);
        if (gr >= 0 && gr < 256)
            v = *(const float4*)(g_hx + (ch << 16) + gr * 256 + c4 * 4);
        *(float4*)(&sx[ch][i][c4 * 4]) = v;
    }
    if (tid < 192) {
        int c4 = tid & 15;
        int i = (tid >> 4) & 3;
        int ch = tid >> 6;
        int gr = base - 1 + i;
        float4 v = make_float4(0.f, 0.f, 0.f, 0.f);
        if (gr >= 0 && gr < 64)
            v = *(const float4*)(g_mx + (ch * 64 + gr) * 64 + c4 * 4);
        smx[ch][i][c4 * 4 + 1] = v.x;
        smx[ch][i][c4 * 4 + 2] = v.y;
        smx[ch][i][c4 * 4 + 3] = v.z;
        smx[ch][i][c4 * 4 + 4] = v.w;
    }
    if (tid < 24) { int ch = tid / 8, i = (tid >> 1) & 3, side = tid & 1; smx[ch][i][side ? 65 : 0] = 0.f; }
    if (tid < 6)  { int j = tid >> 1, side = tid & 1; sh[j][side ? 257 : 0] = 0.f; }

    float w[27];
    #pragma unroll
    for (int k = 0; k < 27; k++) w[k] = __ldg(lw + k);
    float bias = __ldg(lb);
    float mbias = __ldg(mb);
    float mwr[27];
    #pragma unroll
    for (int k = 0; k < 27; k++) mwr[k] = __ldg(mw + k);
    __syncthreads();

    __shared__ float sm[2][64];
    if (tid < 128) {
        int li = 1 + (tid >> 6);
        int mcol = tid & 63;
        float macc = mbias;
        #pragma unroll
        for (int ic = 0; ic < 3; ic++)
            #pragma unroll
            for (int kr = 0; kr < 3; kr++)
                #pragma unroll
                for (int kc = 0; kc < 3; kc++)
                    macc = fmaf(smx[ic][li + kr - 1][mcol + kc], mwr[ic * 9 + kr * 3 + kc], macc);
        float v = fminf(fmaxf(macc, 0.f), 1.f);
        if (v < 0.6f) v = 0.f;
        sm[tid >> 6][mcol] = v;
    }
    __syncthreads();

    int c = tid;
    float acc[3] = {bias, bias, bias};
    #pragma unroll
    for (int ch = 0; ch < 3; ch++) {
        #pragma unroll
        for (int i = 0; i < 5; i++) {
            float vm = (c > 0)   ? sx[ch][i][c - 1] : 0.f;
            float v0 = sx[ch][i][c];
            float vp = (c < 255) ? sx[ch][i][c + 1] : 0.f;
            #pragma unroll
            for (int j = 0; j < 3; j++) {
                int kr = i - j;
                if (kr >= 0 && kr <= 2) {
                    acc[j] = fmaf(w[ch * 9 + kr * 3 + 0], vm,
                             fmaf(w[ch * 9 + kr * 3 + 1], v0,
                             fmaf(w[ch * 9 + kr * 3 + 2], vp, acc[j])));
                }
            }
        }
    }
    #pragma unroll
    for (int j = 0; j < 3; j++) {
        int rj = r - 1 + j;
        float heat = 0.f;
        if (rj >= 0 && rj < 256) {
            float hm = fminf(fmaxf(acc[j], 0.f), 1.f);
            if (hm < 0.4f) hm = 0.f;
            heat = hm * sm[(rj >> 2) - base][c >> 2];
        }
        sh[j][c + 1] = heat;
    }
    __syncthreads();

    float v = sh[1][c + 1];
    bool pk = (v > sh[1][c]) && (v > sh[1][c + 2]) &&
              (v > sh[0][c + 1]) && (v > sh[2][c + 1]);
    unsigned m = __ballot_sync(0xffffffffu, pk);
    if ((c & 31) == 0) g_bits[r * 8 + (c >> 5)] = m;
    out[r * 256 + c] = v;
}

// ---------------- K4: ordered compaction only (warp-shuffle scan) -----------
__global__ __launch_bounds__(256) void k_compact() {
    __shared__ int wsum[8];
    int t = threadIdx.x;
    int lane = t & 31, wid = t >> 5;
    unsigned b[8]; int cnt = 0;
    #pragma unroll
    for (int w = 0; w < 8; w++) { b[w] = g_bits[t * 8 + w]; cnt += __popc(b[w]); }
    // inclusive warp scan of cnt
    int scan = cnt;
    #pragma unroll
    for (int off = 1; off < 32; off <<= 1) {
        int v = __shfl_up_sync(0xffffffffu, scan, off);
        if (lane >= off) scan += v;
    }
    if (lane == 31) wsum[wid] = scan;
    __syncthreads();
    int wbase = 0;
    #pragma unroll
    for (int wwi = 0; wwi < 8; wwi++) wbase += (wwi < wid) ? wsum[wwi] : 0;
    int excl = wbase + scan - cnt;
    int pos = excl;
    #pragma unroll
    for (int w = 0; w < 8; w++) {
        unsigned bits = b[w];
        while (bits) {
            int j = __ffs(bits) - 1; bits &= bits - 1;
            if (pos < 256) { g_coords[2 * pos] = t; g_coords[2 * pos + 1] = w * 32 + j; }
            pos++;
        }
    }
    // total, then fill tail
    int tot = wbase;
    #pragma unroll
    for (int wwi = 0; wwi < 8; wwi++) tot += (wwi >= wid) ? wsum[wwi] : 0;
    // recompute total properly: sum of all warp sums
    __syncthreads();
    int total = 0;
    #pragma unroll
    for (int wwi = 0; wwi < 8; wwi++) total += wsum[wwi];
    if (t >= total) { g_coords[2 * t] = FILL_I; g_coords[2 * t + 1] = FILL_I; }
}

// ---------------- K5: survive (distributed) + classify ----------------------
__global__ __launch_bounds__(256) void k_classify(const float* __restrict__ W, const float* __restrict__ bias,
                                                  float* __restrict__ out) {
    int bx = blockIdx.x;
    int t = threadIdx.x;
    int rme = g_coords[2 * bx], cme = g_coords[2 * bx + 1];
    int rt  = g_coords[2 * t],  ct  = g_coords[2 * t + 1];
    // pairwise reject for candidate bx: any valid t with 1 < d2 < 9
    float dx = (float)rt - (float)rme, dy = (float)ct - (float)cme;
    float d2 = dx * dx + dy * dy;
    int vit = (rt > FILL_I);
    int rej = __syncthreads_or(vit && (d2 > 1.0f) && (d2 < 9.0f));
    int sv = (rme > FILL_I) && !rej;
    if (t == 0) {
        out[OFF_COORDS + 2 * bx]     = (float)rme;
        out[OFF_COORDS + 2 * bx + 1] = (float)cme;
        out[OFF_SURV + bx]           = (float)sv;
    }
    if (!sv) {
        if (t < 7) out[OFF_LOGITS + bx * 7 + t] = 0.f;
        if (t == 0) out[OFF_LABELS + bx] = 0.f;
        return;
    }
    int r0 = min(max(rme, 0), 255);
    int c0 = min(max(cme, 0), 255);
    float part[7] = {0.f, 0.f, 0.f, 0.f, 0.f, 0.f, 0.f};
    #pragma unroll
    for (int it = 0; it < 12; it++) {
        int f = t + it * 256;
        int ch = f >> 10, rem = f & 1023, wr = rem >> 5, wc = rem & 31;
        int rr = r0 + wr - 16, cc = c0 + wc - 16;
        float v = 0.f;
        if (rr >= 0 && rr < 256 && cc >= 0 && cc < 256)
            v = g_hx[(ch << 16) + rr * 256 + cc];
        const float* wrow = W + f * 7;
        #pragma unroll
        for (int k = 0; k < 7; k++) part[k] = fmaf(v, wrow[k], part[k]);
    }
    #pragma unroll
    for (int off = 16; off > 0; off >>= 1)
        #pragma unroll
        for (int k = 0; k < 7; k++)
            part[k] += __shfl_down_sync(0xffffffffu, part[k], off);
    __shared__ float sw[8][7];
    if ((t & 31) == 0)
        #pragma unroll
        for (int k = 0; k < 7; k++) sw[t >> 5][k] = part[k];
    __syncthreads();
    if (t == 0) {
        float l[7], e[7];
        float m = -1e30f;
        #pragma unroll
        for (int k = 0; k < 7; k++) {
            float s = bias[k];
            #pragma unroll
            for (int wi = 0; wi < 8; wi++) s += sw[wi][k];
            l[k] = s; m = fmaxf(m, s);
        }
        float s = 0.f;
        #pragma unroll
        for (int k = 0; k < 7; k++) { e[k] = expf(l[k] - m); s += e[k]; }
        float inv = 1.0f / s;
        int best = 0; float bv = -1e30f;
        #pragma unroll
        for (int k = 0; k < 7; k++) {
            float smv = e[k] * inv;
            out[OFF_LOGITS + bx * 7 + k] = smv;
            if (smv > bv) { bv = smv; best = k; }
        }
        out[OFF_LABELS + bx] = (float)best;
    }
}

// ---------------- launch ------------------------------------------------------
extern "C" void kernel_launch(void* const* d_in, const int* in_sizes, int n_in,
                              void* d_out, int out_size) {
    const float* x    = (const float*)d_in[0];
    const float* locw = (const float*)d_in[1];
    const float* locb = (const float*)d_in[2];
    const float* mskw = (const float*)d_in[3];
    const float* mskb = (const float*)d_in[4];
    const float* lblw = (const float*)d_in[5];
    const float* lblb = (const float*)d_in[6];
    float* out = (float*)d_out;

    k_hresize<<<3240, 256>>>(x);
    k_vresize<<<816, 256>>>();
    k_heatpeak<<<256, 256>>>(locw, locb, mskw, mskb, out);
    k_compact<<<1, 256>>>();
    k_classify<<<256, 256>>>(lblw, lblb, out);
}